// round 7
// baseline (speedup 1.0000x reference)
#include <cuda_runtime.h>
#include <cstdint>

// ---------------------------------------------------------------------------
// ResBlock sparse-conv, round 7: TF32 mma.sync with 2-stage ping-pong pipeline.
//   one __syncthreads per K-chunk, gather LDGs overlap MMA compute,
//   double-buffered smem A/B (dynamic, 74KB) + double-buffered scatter rows,
//   pad_kernel removed (per-tile counts), reduce pair merged, cvtw merged.
// ---------------------------------------------------------------------------

constexpr int CO   = 128;
constexpr int TM   = 128;
constexpr int TKC  = 32;
constexpr int ASTR = 36;    // A row stride (words): conflict-free
constexpr int BSTR = 136;   // B row stride (words): conflict-free
constexpr int MAXN = 300000;
constexpr int STATS_GB = 296;
constexpr int SCATTER_GRID = 296;

// dynamic smem layout (bytes)
constexpr int OFF_A   = 0;        // 2 stages x 128*36*4 = 18432 each
constexpr int OFF_B   = 36864;    // 2 stages x 32*136*4 = 17408 each
constexpr int OFF_SIN = 71680;    // 128 ints
constexpr int OFF_SO  = 72192;    // 2 x 128 ints
constexpr int OFF_SC  = 73216;    // 128 floats
constexpr int OFF_SH  = 73728;    // 128 floats
constexpr int SMEM_GEMM = 74240;

__device__ float g_Y1[(size_t)MAXN * CO];
__device__ float g_Y2[(size_t)MAXN * CO];
__device__ float g_Y4[(size_t)MAXN * CO];
__device__ float g_part[(size_t)2048 * 256];
__device__ float g_scale[4 * CO];
__device__ float g_shift[4 * CO];

__device__ int2 g_pairs31[(size_t)9 * MAXN];
__device__ int2 g_pairs13[(size_t)9 * MAXN];
__device__ int2 g_pairsP[(size_t)27 * MAXN];
__device__ int  g_cnt[64];
__device__ int  g_dirTap[110000];
__device__ int  g_dirBase[110000];
__device__ int  g_dirCnt[110000];
__device__ int  g_nt[4];
__device__ uint32_t g_Wt[884736];   // all weights, tf32-rounded bits

// ---------------- helpers ----------------
__device__ __forceinline__ uint32_t tf32r(float x) {
    uint32_t u;
    asm("cvt.rna.tf32.f32 %0, %1;" : "=r"(u) : "f"(x));
    return u;
}
__device__ __forceinline__ void mma16n8k8(float* c, const uint32_t* a, const uint32_t* b) {
    asm volatile("mma.sync.aligned.m16n8k8.row.col.f32.tf32.tf32.f32 "
                 "{%0,%1,%2,%3}, {%4,%5,%6,%7}, {%8,%9}, {%0,%1,%2,%3};"
                 : "+f"(c[0]), "+f"(c[1]), "+f"(c[2]), "+f"(c[3])
                 : "r"(a[0]), "r"(a[1]), "r"(a[2]), "r"(a[3]), "r"(b[0]), "r"(b[1]));
}
__device__ __forceinline__ void redadd2(float* p, float a, float b) {
    asm volatile("red.global.add.v2.f32 [%0], {%1,%2};"
                 :: "l"(p), "f"(a), "f"(b) : "memory");
}
__device__ __forceinline__ float lrelu(float x) { return (x >= 0.f) ? x : 0.01f * x; }

// ---------------- gather / stage helpers ----------------
template<bool FUSE>
__device__ __forceinline__ void gatherA(const float* __restrict__ src, int c0, bool valid,
                                        const float* __restrict__ sSc,
                                        const float* __restrict__ sSh,
                                        int half, float4* va) {
#pragma unroll
    for (int j = 0; j < 4; ++j) {
        float4 v = make_float4(0.f, 0.f, 0.f, 0.f);
        if (valid) {
            v = __ldg((const float4*)(src + c0 + half * 16) + j);
            if (FUSE) {
                int cc = c0 + half * 16 + j * 4;
                v.x = fmaf(lrelu(v.x), sSc[cc + 0], sSh[cc + 0]);
                v.y = fmaf(lrelu(v.y), sSc[cc + 1], sSh[cc + 1]);
                v.z = fmaf(lrelu(v.z), sSc[cc + 2], sSh[cc + 2]);
                v.w = fmaf(lrelu(v.w), sSc[cc + 3], sSh[cc + 3]);
            }
        }
        va[j] = v;
    }
}
__device__ __forceinline__ void storeA(uint32_t* __restrict__ As, int row, int half,
                                       const float4* va) {
#pragma unroll
    for (int j = 0; j < 4; ++j) {
        uint4 q;
        q.x = tf32r(va[j].x); q.y = tf32r(va[j].y);
        q.z = tf32r(va[j].z); q.w = tf32r(va[j].w);
        *(uint4*)&As[row * ASTR + half * 16 + j * 4] = q;
    }
}
__device__ __forceinline__ void loadB(const uint32_t* __restrict__ Wk, int c0, int tid,
                                      uint4* vb) {
#pragma unroll
    for (int j = 0; j < 4; ++j) {
        int i2 = tid + j * 256;
        int kk = i2 >> 5, c4 = (i2 & 31) << 2;
        vb[j] = __ldg((const uint4*)(Wk + (size_t)(c0 + kk) * CO + c4));
    }
}
__device__ __forceinline__ void storeB(uint32_t* __restrict__ Bs, int tid, const uint4* vb) {
#pragma unroll
    for (int j = 0; j < 4; ++j) {
        int i2 = tid + j * 256;
        int kk = i2 >> 5, c4 = (i2 & 31) << 2;
        *(uint4*)&Bs[kk * BSTR + c4] = vb[j];
    }
}

// MMA core: warp computes 64x32 of the 128x128 tile over one TKC=32 chunk.
__device__ __forceinline__ void core_compute(float (*acc)[4][4],
                                             const uint32_t* __restrict__ As,
                                             const uint32_t* __restrict__ Bs,
                                             int mb, int nb, int lane) {
    const int l3 = lane & 3, l2 = lane >> 2;
#pragma unroll
    for (int ks = 0; ks < TKC; ks += 8) {
        uint32_t bf[4][2];
#pragma unroll
        for (int na = 0; na < 4; ++na) {
            bf[na][0] = Bs[(ks + l3) * BSTR + nb + na * 8 + l2];
            bf[na][1] = Bs[(ks + 4 + l3) * BSTR + nb + na * 8 + l2];
        }
#pragma unroll
        for (int ma = 0; ma < 4; ++ma) {
            const int mrow = mb + ma * 16 + l2;
            uint32_t af[4];
            af[0] = As[mrow * ASTR + ks + l3];
            af[1] = As[(mrow + 8) * ASTR + ks + l3];
            af[2] = As[mrow * ASTR + ks + 4 + l3];
            af[3] = As[(mrow + 8) * ASTR + ks + 4 + l3];
#pragma unroll
            for (int na = 0; na < 4; ++na) mma16n8k8(acc[ma][na], af, bf[na]);
        }
    }
}

// ---------------------------------------------------------------------------
// Weight pre-conversion, single launch over all 5 tensors.
// uint4 region bounds: W1 18432, W1_2 36864, W2 18432, W3 36864, Wp 110592.
// ---------------------------------------------------------------------------
__global__ void cvtw_all(const float* __restrict__ w1, const float* __restrict__ w12,
                         const float* __restrict__ w2, const float* __restrict__ w3,
                         const float* __restrict__ wp, uint32_t* __restrict__ out) {
    int i = blockIdx.x * 256 + threadIdx.x;
    if (i >= 221184) return;
    const float* src;
    int off;
    if      (i < 18432)  { src = w1;  off = 0; }
    else if (i < 55296)  { src = w12; off = 18432; }
    else if (i < 73728)  { src = w2;  off = 55296; }
    else if (i < 110592) { src = w3;  off = 73728; }
    else                 { src = wp;  off = 110592; }
    float4 v = __ldg((const float4*)src + (i - off));
    uint4 q;
    q.x = tf32r(v.x); q.y = tf32r(v.y); q.z = tf32r(v.z); q.w = tf32r(v.w);
    ((uint4*)out)[i] = q;
}

// ---------------------------------------------------------------------------
// Compaction + directory (per-tile valid counts; no pad pass)
// ---------------------------------------------------------------------------
__global__ void compact_kernel(const int* __restrict__ kmap, int K, int M, int center,
                               int2* __restrict__ pairs, int cap, int* __restrict__ cnt) {
    int i = blockIdx.x * 256 + threadIdx.x;
    if (i >= K * M) return;
    int k = i / M;
    if (k == center) return;
    int idx = kmap[i];
    if (idx >= 0) {
        int pos = atomicAdd(&cnt[k], 1);
        pairs[(size_t)k * cap + pos] = make_int2(i - k * M, idx);
    }
}

__global__ void build_dir_kernel(const int* __restrict__ cnt, int K, int cap,
                                 int* __restrict__ tileTap, int* __restrict__ tileBase,
                                 int* __restrict__ tileCnt, int* __restrict__ ntOut) {
    __shared__ int ntk[32], off[32], cks[32];
    if (threadIdx.x == 0) {
        int t = 0;
        for (int k = 0; k < K; ++k) {
            off[k] = t;
            cks[k] = cnt[k];
            ntk[k] = (cks[k] + TM - 1) / TM;
            t += ntk[k];
        }
        *ntOut = t;
    }
    __syncthreads();
    for (int k = 0; k < K; ++k)
        for (int j = threadIdx.x; j < ntk[k]; j += blockDim.x) {
            tileTap[off[k] + j]  = k;
            tileBase[off[k] + j] = k * cap + j * TM;
            int rem = cks[k] - j * TM;
            tileCnt[off[k] + j]  = rem < TM ? rem : TM;
        }
}

// ---------------------------------------------------------------------------
// Dense center-tap GEMM: Out[m] = T(Fin[m]) @ Wc   (T = lrelu+BN if FUSE)
// ---------------------------------------------------------------------------
template<int CIN, bool FUSE>
__global__ void __launch_bounds__(256, 2) center_kernel(
    const float* __restrict__ Fin, const uint32_t* __restrict__ Wt, int M,
    const float* __restrict__ inScale, const float* __restrict__ inShift,
    float* __restrict__ Out)
{
    extern __shared__ char smem[];
    float* sSc = (float*)(smem + OFF_SC);
    float* sSh = (float*)(smem + OFF_SH);

    const int tid  = threadIdx.x;
    const int wid  = tid >> 5, lane = tid & 31;
    const int mb   = (wid & 1) * 64, nbb = (wid >> 1) * 32;
    const int row  = tid >> 1, half = tid & 1;
    constexpr int CHUNKS = CIN / TKC;

    if (FUSE) {
        if (tid < CIN) { sSc[tid] = inScale[tid]; sSh[tid] = inShift[tid]; }
        __syncthreads();
    }

    const int m0 = blockIdx.x * TM;
    const int m  = m0 + row;
    const bool vrow = m < M;
    const float* src = Fin + (size_t)(vrow ? m : 0) * CIN;

    float acc[4][4][4];
#pragma unroll
    for (int ma = 0; ma < 4; ++ma)
#pragma unroll
        for (int na = 0; na < 4; ++na)
#pragma unroll
            for (int p = 0; p < 4; ++p) acc[ma][na][p] = 0.f;

    // fill chunk 0 -> stage 0
    {
        float4 va[4]; uint4 vb[4];
        gatherA<FUSE>(src, 0, vrow, sSc, sSh, half, va);
        loadB(Wt, 0, tid, vb);
        storeA((uint32_t*)(smem + OFF_A), row, half, va);
        storeB((uint32_t*)(smem + OFF_B), tid, vb);
    }
    __syncthreads();

#pragma unroll
    for (int c = 0; c < CHUNKS; ++c) {
        const int s = c & 1;
        float4 va[4]; uint4 vb[4];
        if (c + 1 < CHUNKS) {                       // LDGs in flight during compute
            gatherA<FUSE>(src, (c + 1) * TKC, vrow, sSc, sSh, half, va);
            loadB(Wt, (c + 1) * TKC, tid, vb);
        }
        core_compute(acc, (const uint32_t*)(smem + OFF_A + s * 18432),
                     (const uint32_t*)(smem + OFF_B + s * 17408), mb, nbb, lane);
        if (c + 1 < CHUNKS) {
            storeA((uint32_t*)(smem + OFF_A + (s ^ 1) * 18432), row, half, va);
            storeB((uint32_t*)(smem + OFF_B + (s ^ 1) * 17408), tid, vb);
            __syncthreads();
        }
    }

    const int l3 = lane & 3, l2 = lane >> 2;
#pragma unroll
    for (int ma = 0; ma < 4; ++ma) {
        int r0 = m0 + mb + ma * 16 + l2;
        int r1 = r0 + 8;
#pragma unroll
        for (int na = 0; na < 4; ++na) {
            int col = nbb + na * 8 + 2 * l3;
            if (r0 < M)
                *(float2*)&Out[(size_t)r0 * CO + col] = make_float2(acc[ma][na][0], acc[ma][na][1]);
            if (r1 < M)
                *(float2*)&Out[(size_t)r1 * CO + col] = make_float2(acc[ma][na][2], acc[ma][na][3]);
        }
    }
}

// ---------------------------------------------------------------------------
// Scatter-GEMM over compacted tap tiles; epilogue = red.global.add.v2.f32
// ---------------------------------------------------------------------------
template<int CIN, bool FUSE>
__global__ void __launch_bounds__(256, 2) scatter_kernel(
    const float* __restrict__ Fin, const uint32_t* __restrict__ Wt,
    const int* __restrict__ tileTap, const int* __restrict__ tileBase,
    const int* __restrict__ tileCnt, const int* __restrict__ ntPtr,
    const int2* __restrict__ pairs,
    const float* __restrict__ inScale, const float* __restrict__ inShift,
    float* __restrict__ Out)
{
    extern __shared__ char smem[];
    int*   sIn = (int*)(smem + OFF_SIN);
    int*   sOut = (int*)(smem + OFF_SO);
    float* sSc = (float*)(smem + OFF_SC);
    float* sSh = (float*)(smem + OFF_SH);

    const int tid  = threadIdx.x;
    const int wid  = tid >> 5, lane = tid & 31;
    const int mb   = (wid & 1) * 64, nbb = (wid >> 1) * 32;
    const int row  = tid >> 1, half = tid & 1;
    const int l3   = lane & 3, l2 = lane >> 2;
    constexpr int CHUNKS = CIN / TKC;

    if (FUSE && tid < CIN) { sSc[tid] = inScale[tid]; sSh[tid] = inShift[tid]; }
    const int nTiles = __ldg(ntPtr);

    // preamble: pairs for first tile into registers
    int2 pr = make_int2(-1, 0);
    if (blockIdx.x < nTiles && tid < TM) {
        int base = __ldg(&tileBase[blockIdx.x]);
        int tc   = __ldg(&tileCnt[blockIdx.x]);
        pr = (tid < tc) ? __ldg(&pairs[(size_t)base + tid]) : make_int2(-1, 0);
    }

    int li = 0;
    for (int t = blockIdx.x; t < nTiles; t += gridDim.x, ++li) {
        const int dp = li & 1;
        const int k  = __ldg(&tileTap[t]);
        if (tid < TM) { sIn[tid] = pr.y; sOut[dp * TM + tid] = pr.x; }
        __syncthreads();                       // sIn/sOut visible; FUSE sSc covered (li==0)
        const int idx = sIn[row];
        const uint32_t* Wk = Wt + (size_t)k * CIN * CO;
        const float* src = Fin + (size_t)idx * CIN;

        float acc[4][4][4];
#pragma unroll
        for (int ma = 0; ma < 4; ++ma)
#pragma unroll
            for (int na = 0; na < 4; ++na)
#pragma unroll
                for (int p = 0; p < 4; ++p) acc[ma][na][p] = 0.f;

        // fill chunk 0 -> stage 0 ; prefetch next tile's pairs meanwhile
        {
            float4 va[4]; uint4 vb[4];
            gatherA<FUSE>(src, 0, true, sSc, sSh, half, va);
            loadB(Wk, 0, tid, vb);
            int tn = t + gridDim.x;
            if (tn < nTiles && tid < TM) {
                int base = __ldg(&tileBase[tn]);
                int tc   = __ldg(&tileCnt[tn]);
                pr = (tid < tc) ? __ldg(&pairs[(size_t)base + tid]) : make_int2(-1, 0);
            } else {
                pr = make_int2(-1, 0);
            }
            storeA((uint32_t*)(smem + OFF_A), row, half, va);
            storeB((uint32_t*)(smem + OFF_B), tid, vb);
        }
        __syncthreads();

#pragma unroll
        for (int c = 0; c < CHUNKS; ++c) {
            const int s = c & 1;
            float4 va[4]; uint4 vb[4];
            if (c + 1 < CHUNKS) {
                gatherA<FUSE>(src, (c + 1) * TKC, true, sSc, sSh, half, va);
                loadB(Wk, (c + 1) * TKC, tid, vb);
            }
            core_compute(acc, (const uint32_t*)(smem + OFF_A + s * 18432),
                         (const uint32_t*)(smem + OFF_B + s * 17408), mb, nbb, lane);
            if (c + 1 < CHUNKS) {
                storeA((uint32_t*)(smem + OFF_A + (s ^ 1) * 18432), row, half, va);
                storeB((uint32_t*)(smem + OFF_B + (s ^ 1) * 17408), tid, vb);
                __syncthreads();
            }
        }

        // epilogue: scatter-add using this tile's output rows (sOut[dp])
#pragma unroll
        for (int ma = 0; ma < 4; ++ma) {
            int lr0 = mb + ma * 16 + l2;
            int m0r = sOut[dp * TM + lr0];
            int m1r = sOut[dp * TM + lr0 + 8];
#pragma unroll
            for (int na = 0; na < 4; ++na) {
                int col = nbb + na * 8 + 2 * l3;
                if (m0r >= 0) redadd2(Out + (size_t)m0r * CO + col, acc[ma][na][0], acc[ma][na][1]);
                if (m1r >= 0) redadd2(Out + (size_t)m1r * CO + col, acc[ma][na][2], acc[ma][na][3]);
            }
        }
        // next iteration's top __syncthreads protects sIn/sOut/stage reuse
    }
}

// ---------------------------------------------------------------------------
// BN stats on raw conv output (applies lrelu): partials then single-block final
// ---------------------------------------------------------------------------
__global__ void stats_kernel(const float* __restrict__ Y, int N, float* __restrict__ part) {
    int c    = threadIdx.x & 127;
    int half = threadIdx.x >> 7;
    int rows = (N + gridDim.x - 1) / gridDim.x;
    int r0   = blockIdx.x * rows;
    int r1   = min(N, r0 + rows);
    float s = 0.f, q = 0.f;
    for (int r = r0 + half; r < r1; r += 2) {
        float x = lrelu(__ldg(&Y[(size_t)r * 128 + c]));
        s += x; q += x * x;
    }
    __shared__ float sh[256];
    sh[threadIdx.x] = s; __syncthreads();
    if (half == 0) part[(size_t)blockIdx.x * 256 + c] = sh[c] + sh[128 + c];
    __syncthreads();
    sh[threadIdx.x] = q; __syncthreads();
    if (half == 0) part[(size_t)blockIdx.x * 256 + 128 + c] = sh[c] + sh[128 + c];
}

__global__ void stats_final(const float* __restrict__ part, int nb, float invn,
                            const float* __restrict__ g, const float* __restrict__ b,
                            float* __restrict__ scale, float* __restrict__ shift) {
    int c = threadIdx.x;   // 128 threads
    float s = 0.f, q = 0.f;
    for (int r = 0; r < nb; ++r) {
        s += __ldg(&part[(size_t)r * 256 + c]);
        q += __ldg(&part[(size_t)r * 256 + 128 + c]);
    }
    float mean = s * invn;
    float var  = q * invn - mean * mean;
    float sc   = g[c] * rsqrtf(var + 1e-5f);
    scale[c] = sc;
    shift[c] = b[c] - mean * sc;
}

// resA = BN3(lrelu(y4)) + BN1(lrelu(y2))
__global__ void add_bn_kernel(const float* __restrict__ y4, const float* __restrict__ y2,
                              const float* __restrict__ sc4, const float* __restrict__ sh4,
                              const float* __restrict__ sc2, const float* __restrict__ sh2,
                              float* __restrict__ out, int n4) {
    int i = blockIdx.x * blockDim.x + threadIdx.x;
    if (i >= n4) return;
    int cg = i & 31;
    float4 a  = __ldg((const float4*)y4 + i);
    float4 c  = __ldg((const float4*)y2 + i);
    float4 s4 = __ldg((const float4*)sc4 + cg);
    float4 h4 = __ldg((const float4*)sh4 + cg);
    float4 s2 = __ldg((const float4*)sc2 + cg);
    float4 h2 = __ldg((const float4*)sh2 + cg);
    float4 o;
    o.x = fmaf(lrelu(a.x), s4.x, h4.x) + fmaf(lrelu(c.x), s2.x, h2.x);
    o.y = fmaf(lrelu(a.y), s4.y, h4.y) + fmaf(lrelu(c.y), s2.y, h2.y);
    o.z = fmaf(lrelu(a.z), s4.z, h4.z) + fmaf(lrelu(c.z), s2.z, h2.z);
    o.w = fmaf(lrelu(a.w), s4.w, h4.w) + fmaf(lrelu(c.w), s2.w, h2.w);
    ((float4*)out)[i] = o;
}

extern "C" void kernel_launch(void* const* d_in, const int* in_sizes, int n_in,
                              void* d_out, int out_size) {
    const float* feats = (const float*)d_in[0];
    const int*   map31 = (const int*)d_in[1];
    const int*   map13 = (const int*)d_in[2];
    const int*   mpool = (const int*)d_in[3];
    const float* W1    = (const float*)d_in[4];
    const float* W1_2  = (const float*)d_in[5];
    const float* W2    = (const float*)d_in[6];
    const float* W3    = (const float*)d_in[7];
    const float* Wp    = (const float*)d_in[8];
    const float* g0    = (const float*)d_in[9];
    const float* b0    = (const float*)d_in[10];
    const float* g0_2  = (const float*)d_in[11];
    const float* b0_2  = (const float*)d_in[12];
    const float* g1    = (const float*)d_in[13];
    const float* b1    = (const float*)d_in[14];
    const float* g2    = (const float*)d_in[15];
    const float* b2    = (const float*)d_in[16];

    int N = in_sizes[0] / 64;
    int M = in_sizes[3] / 27;

    float *Y1, *Y2, *Y4, *part, *scaleA, *shiftA;
    int2 *p31, *p13, *pP;
    int  *cnt, *dTap, *dBase, *dCnt, *nt;
    uint32_t* Wt;
    cudaGetSymbolAddress((void**)&Y1, g_Y1);
    cudaGetSymbolAddress((void**)&Y2, g_Y2);
    cudaGetSymbolAddress((void**)&Y4, g_Y4);
    cudaGetSymbolAddress((void**)&part, g_part);
    cudaGetSymbolAddress((void**)&scaleA, g_scale);
    cudaGetSymbolAddress((void**)&shiftA, g_shift);
    cudaGetSymbolAddress((void**)&p31, g_pairs31);
    cudaGetSymbolAddress((void**)&p13, g_pairs13);
    cudaGetSymbolAddress((void**)&pP,  g_pairsP);
    cudaGetSymbolAddress((void**)&cnt, g_cnt);
    cudaGetSymbolAddress((void**)&dTap, g_dirTap);
    cudaGetSymbolAddress((void**)&dBase, g_dirBase);
    cudaGetSymbolAddress((void**)&dCnt, g_dirCnt);
    cudaGetSymbolAddress((void**)&nt, g_nt);
    cudaGetSymbolAddress((void**)&Wt, g_Wt);

    float* resB = (float*)d_out;
    float* resA = (float*)d_out + (size_t)M * CO;

    int nb = (N + TM - 1) / TM;
    float invn = 1.0f / (float)N;

    // dynamic smem opt-in
    cudaFuncSetAttribute(center_kernel<64, false>,  cudaFuncAttributeMaxDynamicSharedMemorySize, SMEM_GEMM);
    cudaFuncSetAttribute(center_kernel<128, true>,  cudaFuncAttributeMaxDynamicSharedMemorySize, SMEM_GEMM);
    cudaFuncSetAttribute(scatter_kernel<64, false>, cudaFuncAttributeMaxDynamicSharedMemorySize, SMEM_GEMM);
    cudaFuncSetAttribute(scatter_kernel<128, true>, cudaFuncAttributeMaxDynamicSharedMemorySize, SMEM_GEMM);
    cudaFuncSetAttribute(scatter_kernel<128, false>, cudaFuncAttributeMaxDynamicSharedMemorySize, SMEM_GEMM);

    int* dTap31 = dTap;          int* dBase31 = dBase;          int* dCnt31 = dCnt;
    int* dTap13 = dTap + 20000;  int* dBase13 = dBase + 20000;  int* dCnt13 = dCnt + 20000;
    int* dTapP  = dTap + 40000;  int* dBaseP  = dBase + 40000;  int* dCntP  = dCnt + 40000;

    // pre-converted weight regions (word offsets)
    uint32_t* T1  = Wt;
    uint32_t* T12 = Wt + 73728;
    uint32_t* T2  = Wt + 221184;
    uint32_t* T3  = Wt + 294912;
    uint32_t* Tp  = Wt + 442368;
    cvtw_all<<<(221184 + 255) / 256, 256>>>(W1, W1_2, W2, W3, Wp, Wt);

    // ---- one-time compaction of the three maps ----
    cudaMemsetAsync(cnt, 0, 64 * sizeof(int));
    compact_kernel<<<(9 * N + 255) / 256, 256>>>(map31, 9, N, 4, p31, N, cnt);
    compact_kernel<<<(9 * N + 255) / 256, 256>>>(map13, 9, N, 4, p13, N, cnt + 16);
    compact_kernel<<<(27 * M + 255) / 256, 256>>>(mpool, 27, M, -1, pP, M, cnt + 32);
    build_dir_kernel<<<1, 256>>>(cnt, 9, N, dTap31, dBase31, dCnt31, nt + 0);
    build_dir_kernel<<<1, 256>>>(cnt + 16, 9, N, dTap13, dBase13, dCnt13, nt + 1);
    build_dir_kernel<<<1, 256>>>(cnt + 32, 27, M, dTapP, dBaseP, dCntP, nt + 2);

    // ---- conv1 (3,1,3): feats -> Y1 (raw) ----
    center_kernel<64, false><<<nb, 256, SMEM_GEMM>>>(feats, T1 + (size_t)4 * 64 * CO, N,
                                                     nullptr, nullptr, Y1);
    scatter_kernel<64, false><<<SCATTER_GRID, 256, SMEM_GEMM>>>(
        feats, T1, dTap31, dBase31, dCnt31, nt + 0, p31, nullptr, nullptr, Y1);
    stats_kernel<<<STATS_GB, 256>>>(Y1, N, part);
    stats_final<<<1, 128>>>(part, STATS_GB, invn, g0, b0, scaleA + 0, shiftA + 0);

    // ---- conv1_2 (1,3,3): BN0(lrelu(Y1)) -> Y2 (raw) ----
    center_kernel<128, true><<<nb, 256, SMEM_GEMM>>>(Y1, T12 + (size_t)4 * 128 * CO, N,
                                                     scaleA + 0, shiftA + 0, Y2);
    scatter_kernel<128, true><<<SCATTER_GRID, 256, SMEM_GEMM>>>(
        Y1, T12, dTap13, dBase13, dCnt13, nt + 1, p13, scaleA + 0, shiftA + 0, Y2);
    stats_kernel<<<STATS_GB, 256>>>(Y2, N, part);
    stats_final<<<1, 128>>>(part, STATS_GB, invn, g0_2, b0_2, scaleA + 128, shiftA + 128);

    // ---- conv2 (1,3,3): feats -> Y3 (reuse Y1) ----
    center_kernel<64, false><<<nb, 256, SMEM_GEMM>>>(feats, T2 + (size_t)4 * 64 * CO, N,
                                                     nullptr, nullptr, Y1);
    scatter_kernel<64, false><<<SCATTER_GRID, 256, SMEM_GEMM>>>(
        feats, T2, dTap13, dBase13, dCnt13, nt + 1, p13, nullptr, nullptr, Y1);
    stats_kernel<<<STATS_GB, 256>>>(Y1, N, part);
    stats_final<<<1, 128>>>(part, STATS_GB, invn, g1, b1, scaleA + 256, shiftA + 256);

    // ---- conv3 (3,1,3): BN2(lrelu(Y3)) -> Y4 (raw) ----
    center_kernel<128, true><<<nb, 256, SMEM_GEMM>>>(Y1, T3 + (size_t)4 * 128 * CO, N,
                                                     scaleA + 256, shiftA + 256, Y4);
    scatter_kernel<128, true><<<SCATTER_GRID, 256, SMEM_GEMM>>>(
        Y1, T3, dTap31, dBase31, dCnt31, nt + 0, p31, scaleA + 256, shiftA + 256, Y4);
    stats_kernel<<<STATS_GB, 256>>>(Y4, N, part);
    stats_final<<<1, 128>>>(part, STATS_GB, invn, g2, b2, scaleA + 384, shiftA + 384);

    // ---- resA = BN3(lrelu(Y4)) + BN1(lrelu(Y2)) ----
    int n4 = N * (CO / 4);
    add_bn_kernel<<<(n4 + 255) / 256, 256>>>(Y4, Y2, scaleA + 384, shiftA + 384,
                                             scaleA + 128, shiftA + 128, resA, n4);

    // ---- pool conv (3,3,3)/(2,2,1): resA -> resB ----
    cudaMemsetAsync(resB, 0, (size_t)M * CO * sizeof(float));
    scatter_kernel<128, false><<<SCATTER_GRID, 256, SMEM_GEMM>>>(
        resA, Tp, dTapP, dBaseP, dCntP, nt + 2, pP, nullptr, nullptr, resB);
}

// round 8
// speedup vs baseline: 1.4444x; 1.4444x over previous
#include <cuda_runtime.h>
#include <cstdint>

// ---------------------------------------------------------------------------
// ResBlock sparse-conv, round 8: round-6 TF32 mma.sync kernels (proven)
// + warp-aggregated compaction (round-7 profiling showed contended atomicAdd
//   in compact_kernel cost ~750us across the three maps).
// ---------------------------------------------------------------------------

constexpr int CO   = 128;
constexpr int TM   = 128;
constexpr int TKC  = 32;
constexpr int ASTR = 36;    // A row stride (words): conflict-free
constexpr int BSTR = 136;   // B row stride (words): conflict-free
constexpr int MAXN = 300000;
constexpr int STATS_GB = 2048;
constexpr int SCATTER_GRID = 296;

__device__ float g_Y1[(size_t)MAXN * CO];
__device__ float g_Y2[(size_t)MAXN * CO];
__device__ float g_Y4[(size_t)MAXN * CO];
__device__ float g_part[(size_t)STATS_GB * 256];
__device__ float g_part2[64 * 256];
__device__ float g_scale[4 * CO];
__device__ float g_shift[4 * CO];

__device__ int2 g_pairs31[(size_t)9 * MAXN];
__device__ int2 g_pairs13[(size_t)9 * MAXN];
__device__ int2 g_pairsP[(size_t)27 * MAXN];
__device__ int  g_cnt[64];
__device__ int  g_dirTap[110000];
__device__ int  g_dirBase[110000];
__device__ int  g_nt[4];
__device__ uint32_t g_Wt[884736];   // all weights, tf32-rounded bits

// ---------------- helpers ----------------
__device__ __forceinline__ uint32_t tf32r(float x) {
    uint32_t u;
    asm("cvt.rna.tf32.f32 %0, %1;" : "=r"(u) : "f"(x));
    return u;
}
__device__ __forceinline__ void mma16n8k8(float* c, const uint32_t* a, const uint32_t* b) {
    asm volatile("mma.sync.aligned.m16n8k8.row.col.f32.tf32.tf32.f32 "
                 "{%0,%1,%2,%3}, {%4,%5,%6,%7}, {%8,%9}, {%0,%1,%2,%3};"
                 : "+f"(c[0]), "+f"(c[1]), "+f"(c[2]), "+f"(c[3])
                 : "r"(a[0]), "r"(a[1]), "r"(a[2]), "r"(a[3]), "r"(b[0]), "r"(b[1]));
}
__device__ __forceinline__ void redadd2(float* p, float a, float b) {
    asm volatile("red.global.add.v2.f32 [%0], {%1,%2};"
                 :: "l"(p), "f"(a), "f"(b) : "memory");
}
__device__ __forceinline__ float lrelu(float x) { return (x >= 0.f) ? x : 0.01f * x; }

// ---------------------------------------------------------------------------
// Weight pre-conversion, single launch over all 5 tensors.
// ---------------------------------------------------------------------------
__global__ void cvtw_all(const float* __restrict__ w1, const float* __restrict__ w12,
                         const float* __restrict__ w2, const float* __restrict__ w3,
                         const float* __restrict__ wp, uint32_t* __restrict__ out) {
    int i = blockIdx.x * 256 + threadIdx.x;
    if (i >= 221184) return;
    const float* src;
    int off;
    if      (i < 18432)  { src = w1;  off = 0; }
    else if (i < 55296)  { src = w12; off = 18432; }
    else if (i < 73728)  { src = w2;  off = 55296; }
    else if (i < 110592) { src = w3;  off = 73728; }
    else                 { src = wp;  off = 110592; }
    float4 v = __ldg((const float4*)src + (i - off));
    uint4 q;
    q.x = tf32r(v.x); q.y = tf32r(v.y); q.z = tf32r(v.z); q.w = tf32r(v.w);
    ((uint4*)out)[i] = q;
}

// ---------------------------------------------------------------------------
// Warp-aggregated compaction: one atomicAdd per warp per tap-group.
// (No early returns — all 32 lanes reach the sync intrinsics.)
// ---------------------------------------------------------------------------
__global__ void compact_kernel(const int* __restrict__ kmap, int K, int M, int center,
                               int2* __restrict__ pairs, int cap, int* __restrict__ cnt) {
    int i = blockIdx.x * 256 + threadIdx.x;
    bool inb = i < K * M;
    int k = 0, idx = -1;
    if (inb) {
        k = i / M;
        if (k != center) idx = __ldg(&kmap[i]);
    }
    bool valid = inb && (k != center) && (idx >= 0);
    unsigned samek  = __match_any_sync(0xffffffffu, k);
    unsigned voters = samek & __ballot_sync(0xffffffffu, valid);
    if (valid) {
        unsigned lanebit = 1u << (threadIdx.x & 31);
        int leader = __ffs(voters) - 1;
        int rank   = __popc(voters & (lanebit - 1));
        int base = 0;
        if ((int)(threadIdx.x & 31) == leader)
            base = atomicAdd(&cnt[k], __popc(voters));
        base = __shfl_sync(voters, base, leader);
        pairs[(size_t)k * cap + base + rank] = make_int2(i - k * M, idx);
    }
}

__global__ void pad_kernel(const int* __restrict__ cnt, int2* __restrict__ pairs, int cap) {
    int k = blockIdx.x;
    int c = cnt[k];
    int e = ((c + TM - 1) / TM) * TM;
    for (int j = c + threadIdx.x; j < e; j += blockDim.x)
        pairs[(size_t)k * cap + j] = make_int2(-1, 0);
}

__global__ void build_dir_kernel(const int* __restrict__ cnt, int K, int cap,
                                 int* __restrict__ tileTap, int* __restrict__ tileBase,
                                 int* __restrict__ ntOut) {
    __shared__ int ntk[32], off[32];
    if (threadIdx.x == 0) {
        int t = 0;
        for (int k = 0; k < K; ++k) {
            off[k] = t;
            ntk[k] = (cnt[k] + TM - 1) / TM;
            t += ntk[k];
        }
        *ntOut = t;
    }
    __syncthreads();
    for (int k = 0; k < K; ++k)
        for (int j = threadIdx.x; j < ntk[k]; j += blockDim.x) {
            tileTap[off[k] + j]  = k;
            tileBase[off[k] + j] = k * cap + j * TM;
        }
}

// ---------------------------------------------------------------------------
// MMA core: warp computes 64x32 of the 128x128 tile over a TK=32 chunk.
// ---------------------------------------------------------------------------
__device__ __forceinline__ void core_compute(float (*acc)[4][4],
                                             const uint32_t* __restrict__ As,
                                             const uint32_t* __restrict__ Bs,
                                             int mb, int nb, int lane) {
    const int l3 = lane & 3, l2 = lane >> 2;
#pragma unroll
    for (int ks = 0; ks < TKC; ks += 8) {
        uint32_t bf[4][2];
#pragma unroll
        for (int na = 0; na < 4; ++na) {
            bf[na][0] = Bs[(ks + l3) * BSTR + nb + na * 8 + l2];
            bf[na][1] = Bs[(ks + 4 + l3) * BSTR + nb + na * 8 + l2];
        }
#pragma unroll
        for (int ma = 0; ma < 4; ++ma) {
            const int mrow = mb + ma * 16 + l2;
            uint32_t af[4];
            af[0] = As[mrow * ASTR + ks + l3];
            af[1] = As[(mrow + 8) * ASTR + ks + l3];
            af[2] = As[mrow * ASTR + ks + 4 + l3];
            af[3] = As[(mrow + 8) * ASTR + ks + 4 + l3];
#pragma unroll
            for (int na = 0; na < 4; ++na) mma16n8k8(acc[ma][na], af, bf[na]);
        }
    }
}

// ---------------------------------------------------------------------------
// Dense center-tap GEMM: Out[m] = T(Fin[m]) @ Wc   (T = lrelu+BN if FUSE)
// ---------------------------------------------------------------------------
template<int CIN, bool FUSE>
__global__ void __launch_bounds__(256, 2) center_kernel(
    const float* __restrict__ Fin, const uint32_t* __restrict__ Wt, int M,
    const float* __restrict__ inScale, const float* __restrict__ inShift,
    float* __restrict__ Out)
{
    __shared__ uint32_t As[TM * ASTR];
    __shared__ uint32_t Bs[TKC * BSTR];
    __shared__ float sSc[128], sSh[128];

    const int tid  = threadIdx.x;
    const int m0   = blockIdx.x * TM;
    const int wid  = tid >> 5, lane = tid & 31;
    const int mb   = (wid & 1) * 64, nb = (wid >> 1) * 32;
    const int row  = tid >> 1, half = tid & 1;
    constexpr int CHUNKS = CIN / TKC;

    if (FUSE && tid < CIN) { sSc[tid] = inScale[tid]; sSh[tid] = inShift[tid]; }
    __syncthreads();

    float acc[4][4][4];
#pragma unroll
    for (int ma = 0; ma < 4; ++ma)
#pragma unroll
        for (int na = 0; na < 4; ++na)
#pragma unroll
            for (int p = 0; p < 4; ++p) acc[ma][na][p] = 0.f;

    const int m = m0 + row;
    float4 va[4];

    // prefetch chunk 0
    {
#pragma unroll
        for (int j = 0; j < 4; ++j) {
            float4 v = make_float4(0.f, 0.f, 0.f, 0.f);
            if (m < M) {
                v = __ldg((const float4*)(Fin + (size_t)m * CIN + half * 16) + j);
                if (FUSE) {
                    int c = half * 16 + j * 4;
                    v.x = fmaf(lrelu(v.x), sSc[c + 0], sSh[c + 0]);
                    v.y = fmaf(lrelu(v.y), sSc[c + 1], sSh[c + 1]);
                    v.z = fmaf(lrelu(v.z), sSc[c + 2], sSh[c + 2]);
                    v.w = fmaf(lrelu(v.w), sSc[c + 3], sSh[c + 3]);
                }
            }
            va[j] = v;
        }
    }

#pragma unroll 1
    for (int c = 0; c < CHUNKS; ++c) {
        const int c0 = c * TKC;
        __syncthreads();
#pragma unroll
        for (int j = 0; j < 4; ++j) {
            uint4 q;
            q.x = tf32r(va[j].x); q.y = tf32r(va[j].y);
            q.z = tf32r(va[j].z); q.w = tf32r(va[j].w);
            *(uint4*)&As[row * ASTR + half * 16 + j * 4] = q;
        }
#pragma unroll
        for (int j = 0; j < 4; ++j) {
            int i2 = tid + j * 256;
            int kk = i2 >> 5, c4 = (i2 & 31) << 2;
            uint4 b = __ldg((const uint4*)(Wt + (size_t)(c0 + kk) * CO + c4));
            *(uint4*)&Bs[kk * BSTR + c4] = b;
        }
        __syncthreads();
        if (c + 1 < CHUNKS) {
            const int cn = c0 + TKC;
#pragma unroll
            for (int j = 0; j < 4; ++j) {
                float4 v = make_float4(0.f, 0.f, 0.f, 0.f);
                if (m < M) {
                    v = __ldg((const float4*)(Fin + (size_t)m * CIN + cn + half * 16) + j);
                    if (FUSE) {
                        int cc = cn + half * 16 + j * 4;
                        v.x = fmaf(lrelu(v.x), sSc[cc + 0], sSh[cc + 0]);
                        v.y = fmaf(lrelu(v.y), sSc[cc + 1], sSh[cc + 1]);
                        v.z = fmaf(lrelu(v.z), sSc[cc + 2], sSh[cc + 2]);
                        v.w = fmaf(lrelu(v.w), sSc[cc + 3], sSh[cc + 3]);
                    }
                }
                va[j] = v;
            }
        }
        core_compute(acc, As, Bs, mb, nb, lane);
    }

    const int l3 = lane & 3, l2 = lane >> 2;
#pragma unroll
    for (int ma = 0; ma < 4; ++ma) {
        int r0 = m0 + mb + ma * 16 + l2;
        int r1 = r0 + 8;
#pragma unroll
        for (int na = 0; na < 4; ++na) {
            int col = nb + na * 8 + 2 * l3;
            if (r0 < M)
                *(float2*)&Out[(size_t)r0 * CO + col] = make_float2(acc[ma][na][0], acc[ma][na][1]);
            if (r1 < M)
                *(float2*)&Out[(size_t)r1 * CO + col] = make_float2(acc[ma][na][2], acc[ma][na][3]);
        }
    }
}

// ---------------------------------------------------------------------------
// Scatter-GEMM over compacted tap tiles; epilogue = red.global.add.v2.f32
// ---------------------------------------------------------------------------
template<int CIN, bool FUSE>
__global__ void __launch_bounds__(256, 2) scatter_kernel(
    const float* __restrict__ Fin, const uint32_t* __restrict__ Wt,
    const int* __restrict__ tileTap, const int* __restrict__ tileBase,
    const int* __restrict__ ntPtr, const int2* __restrict__ pairs,
    const float* __restrict__ inScale, const float* __restrict__ inShift,
    float* __restrict__ Out)
{
    __shared__ uint32_t As[TM * ASTR];
    __shared__ uint32_t Bs[TKC * BSTR];
    __shared__ int   sM[TM], sI[TM];
    __shared__ float sSc[128], sSh[128];

    const int tid  = threadIdx.x;
    const int wid  = tid >> 5, lane = tid & 31;
    const int mb   = (wid & 1) * 64, nb = (wid >> 1) * 32;
    const int row  = tid >> 1, half = tid & 1;
    const int l3   = lane & 3, l2 = lane >> 2;
    constexpr int CHUNKS = CIN / TKC;

    if (FUSE && tid < CIN) { sSc[tid] = inScale[tid]; sSh[tid] = inShift[tid]; }
    const int nTiles = __ldg(ntPtr);

    for (int t = blockIdx.x; t < nTiles; t += gridDim.x) {
        __syncthreads();
        const int k    = __ldg(&tileTap[t]);
        const int base = __ldg(&tileBase[t]);
        if (tid < TM) {
            int2 pr = __ldg(&pairs[(size_t)base + tid]);
            sM[tid] = pr.x;
            sI[tid] = pr.y;
        }
        __syncthreads();
        const uint32_t* Wk = Wt + (size_t)k * CIN * CO;
        const int idx = sI[row];

        float acc[4][4][4];
#pragma unroll
        for (int ma = 0; ma < 4; ++ma)
#pragma unroll
            for (int na = 0; na < 4; ++na)
#pragma unroll
                for (int p = 0; p < 4; ++p) acc[ma][na][p] = 0.f;

        float4 va[4];
#pragma unroll
        for (int j = 0; j < 4; ++j) {
            float4 v = __ldg((const float4*)(Fin + (size_t)idx * CIN + half * 16) + j);
            if (FUSE) {
                int cc = half * 16 + j * 4;
                v.x = fmaf(lrelu(v.x), sSc[cc + 0], sSh[cc + 0]);
                v.y = fmaf(lrelu(v.y), sSc[cc + 1], sSh[cc + 1]);
                v.z = fmaf(lrelu(v.z), sSc[cc + 2], sSh[cc + 2]);
                v.w = fmaf(lrelu(v.w), sSc[cc + 3], sSh[cc + 3]);
            }
            va[j] = v;
        }

#pragma unroll 1
        for (int c = 0; c < CHUNKS; ++c) {
            const int c0 = c * TKC;
            __syncthreads();
#pragma unroll
            for (int j = 0; j < 4; ++j) {
                uint4 q;
                q.x = tf32r(va[j].x); q.y = tf32r(va[j].y);
                q.z = tf32r(va[j].z); q.w = tf32r(va[j].w);
                *(uint4*)&As[row * ASTR + half * 16 + j * 4] = q;
            }
#pragma unroll
            for (int j = 0; j < 4; ++j) {
                int i2 = tid + j * 256;
                int kk = i2 >> 5, c4 = (i2 & 31) << 2;
                uint4 b = __ldg((const uint4*)(Wk + (size_t)(c0 + kk) * CO + c4));
                *(uint4*)&Bs[kk * BSTR + c4] = b;
            }
            __syncthreads();
            if (c + 1 < CHUNKS) {
                const int cn = c0 + TKC;
#pragma unroll
                for (int j = 0; j < 4; ++j) {
                    float4 v = __ldg((const float4*)(Fin + (size_t)idx * CIN + cn + half * 16) + j);
                    if (FUSE) {
                        int cc = cn + half * 16 + j * 4;
                        v.x = fmaf(lrelu(v.x), sSc[cc + 0], sSh[cc + 0]);
                        v.y = fmaf(lrelu(v.y), sSc[cc + 1], sSh[cc + 1]);
                        v.z = fmaf(lrelu(v.z), sSc[cc + 2], sSh[cc + 2]);
                        v.w = fmaf(lrelu(v.w), sSc[cc + 3], sSh[cc + 3]);
                    }
                    va[j] = v;
                }
            }
            core_compute(acc, As, Bs, mb, nb, lane);
        }

#pragma unroll
        for (int ma = 0; ma < 4; ++ma) {
            int lr0 = mb + ma * 16 + l2;
            int m0r = sM[lr0];
            int m1r = sM[lr0 + 8];
#pragma unroll
            for (int na = 0; na < 4; ++na) {
                int col = nb + na * 8 + 2 * l3;
                if (m0r >= 0) redadd2(Out + (size_t)m0r * CO + col, acc[ma][na][0], acc[ma][na][1]);
                if (m1r >= 0) redadd2(Out + (size_t)m1r * CO + col, acc[ma][na][2], acc[ma][na][3]);
            }
        }
    }
}

// ---------------------------------------------------------------------------
// BN stats on raw conv output (applies lrelu)
// ---------------------------------------------------------------------------
__global__ void stats_kernel(const float* __restrict__ Y, int N, float* __restrict__ part) {
    int c    = threadIdx.x & 127;
    int half = threadIdx.x >> 7;
    int rows = (N + gridDim.x - 1) / gridDim.x;
    int r0   = blockIdx.x * rows;
    int r1   = min(N, r0 + rows);
    float s = 0.f, q = 0.f;
    for (int r = r0 + half; r < r1; r += 2) {
        float x = lrelu(__ldg(&Y[(size_t)r * 128 + c]));
        s += x; q += x * x;
    }
    __shared__ float sh[256];
    sh[threadIdx.x] = s; __syncthreads();
    if (half == 0) part[(size_t)blockIdx.x * 256 + c] = sh[c] + sh[128 + c];
    __syncthreads();
    sh[threadIdx.x] = q; __syncthreads();
    if (half == 0) part[(size_t)blockIdx.x * 256 + 128 + c] = sh[c] + sh[128 + c];
}

__global__ void reduce1_kernel(const float* __restrict__ part, int nb,
                               float* __restrict__ part2) {
    int rpb = (nb + 63) >> 6;
    int r0  = blockIdx.x * rpb;
    int r1  = min(nb, r0 + rpb);
    float s = 0.f;
    for (int r = r0; r < r1; ++r) s += part[(size_t)r * 256 + threadIdx.x];
    part2[blockIdx.x * 256 + threadIdx.x] = s;
}

__global__ void reduce2_kernel(const float* __restrict__ part2, float invn,
                               const float* __restrict__ g, const float* __restrict__ b,
                               float* __restrict__ scale, float* __restrict__ shift) {
    int c = threadIdx.x;
    float s = 0.f, q = 0.f;
#pragma unroll
    for (int j = 0; j < 64; ++j) {
        s += part2[j * 256 + c];
        q += part2[j * 256 + 128 + c];
    }
    float mean = s * invn;
    float var  = q * invn - mean * mean;
    float sc   = g[c] * rsqrtf(var + 1e-5f);
    scale[c] = sc;
    shift[c] = b[c] - mean * sc;
}

__global__ void add_bn_kernel(const float* __restrict__ y4, const float* __restrict__ y2,
                              const float* __restrict__ sc4, const float* __restrict__ sh4,
                              const float* __restrict__ sc2, const float* __restrict__ sh2,
                              float* __restrict__ out, int n4) {
    int i = blockIdx.x * blockDim.x + threadIdx.x;
    if (i >= n4) return;
    int cg = i & 31;
    float4 a  = __ldg((const float4*)y4 + i);
    float4 c  = __ldg((const float4*)y2 + i);
    float4 s4 = __ldg((const float4*)sc4 + cg);
    float4 h4 = __ldg((const float4*)sh4 + cg);
    float4 s2 = __ldg((const float4*)sc2 + cg);
    float4 h2 = __ldg((const float4*)sh2 + cg);
    float4 o;
    o.x = fmaf(lrelu(a.x), s4.x, h4.x) + fmaf(lrelu(c.x), s2.x, h2.x);
    o.y = fmaf(lrelu(a.y), s4.y, h4.y) + fmaf(lrelu(c.y), s2.y, h2.y);
    o.z = fmaf(lrelu(a.z), s4.z, h4.z) + fmaf(lrelu(c.z), s2.z, h2.z);
    o.w = fmaf(lrelu(a.w), s4.w, h4.w) + fmaf(lrelu(c.w), s2.w, h2.w);
    ((float4*)out)[i] = o;
}

extern "C" void kernel_launch(void* const* d_in, const int* in_sizes, int n_in,
                              void* d_out, int out_size) {
    const float* feats = (const float*)d_in[0];
    const int*   map31 = (const int*)d_in[1];
    const int*   map13 = (const int*)d_in[2];
    const int*   mpool = (const int*)d_in[3];
    const float* W1    = (const float*)d_in[4];
    const float* W1_2  = (const float*)d_in[5];
    const float* W2    = (const float*)d_in[6];
    const float* W3    = (const float*)d_in[7];
    const float* Wp    = (const float*)d_in[8];
    const float* g0    = (const float*)d_in[9];
    const float* b0    = (const float*)d_in[10];
    const float* g0_2  = (const float*)d_in[11];
    const float* b0_2  = (const float*)d_in[12];
    const float* g1    = (const float*)d_in[13];
    const float* b1    = (const float*)d_in[14];
    const float* g2    = (const float*)d_in[15];
    const float* b2    = (const float*)d_in[16];

    int N = in_sizes[0] / 64;
    int M = in_sizes[3] / 27;

    float *Y1, *Y2, *Y4, *part, *part2, *scaleA, *shiftA;
    int2 *p31, *p13, *pP;
    int  *cnt, *dTap, *dBase, *nt;
    uint32_t* Wt;
    cudaGetSymbolAddress((void**)&Y1, g_Y1);
    cudaGetSymbolAddress((void**)&Y2, g_Y2);
    cudaGetSymbolAddress((void**)&Y4, g_Y4);
    cudaGetSymbolAddress((void**)&part, g_part);
    cudaGetSymbolAddress((void**)&part2, g_part2);
    cudaGetSymbolAddress((void**)&scaleA, g_scale);
    cudaGetSymbolAddress((void**)&shiftA, g_shift);
    cudaGetSymbolAddress((void**)&p31, g_pairs31);
    cudaGetSymbolAddress((void**)&p13, g_pairs13);
    cudaGetSymbolAddress((void**)&pP,  g_pairsP);
    cudaGetSymbolAddress((void**)&cnt, g_cnt);
    cudaGetSymbolAddress((void**)&dTap, g_dirTap);
    cudaGetSymbolAddress((void**)&dBase, g_dirBase);
    cudaGetSymbolAddress((void**)&nt, g_nt);
    cudaGetSymbolAddress((void**)&Wt, g_Wt);

    float* resB = (float*)d_out;
    float* resA = (float*)d_out + (size_t)M * CO;

    int nb = (N + TM - 1) / TM;
    float invn = 1.0f / (float)N;

    int* dTap31 = dTap;          int* dBase31 = dBase;
    int* dTap13 = dTap + 20000;  int* dBase13 = dBase + 20000;
    int* dTapP  = dTap + 40000;  int* dBaseP  = dBase + 40000;

    // pre-converted weight regions (word offsets)
    uint32_t* T1  = Wt;
    uint32_t* T12 = Wt + 73728;
    uint32_t* T2  = Wt + 221184;
    uint32_t* T3  = Wt + 294912;
    uint32_t* Tp  = Wt + 442368;
    cvtw_all<<<(221184 + 255) / 256, 256>>>(W1, W1_2, W2, W3, Wp, Wt);

    // ---- one-time compaction of the three maps (warp-aggregated atomics) ----
    cudaMemsetAsync(cnt, 0, 64 * sizeof(int));
    compact_kernel<<<(9 * N + 255) / 256, 256>>>(map31, 9, N, 4, p31, N, cnt);
    compact_kernel<<<(9 * N + 255) / 256, 256>>>(map13, 9, N, 4, p13, N, cnt + 16);
    compact_kernel<<<(27 * M + 255) / 256, 256>>>(mpool, 27, M, -1, pP, M, cnt + 32);
    pad_kernel<<<9, 128>>>(cnt, p31, N);
    pad_kernel<<<9, 128>>>(cnt + 16, p13, N);
    pad_kernel<<<27, 128>>>(cnt + 32, pP, M);
    build_dir_kernel<<<1, 256>>>(cnt, 9, N, dTap31, dBase31, nt + 0);
    build_dir_kernel<<<1, 256>>>(cnt + 16, 9, N, dTap13, dBase13, nt + 1);
    build_dir_kernel<<<1, 256>>>(cnt + 32, 27, M, dTapP, dBaseP, nt + 2);

    // ---- conv1 (3,1,3): feats -> Y1 (raw) ----
    center_kernel<64, false><<<nb, 256>>>(feats, T1 + (size_t)4 * 64 * CO, N,
                                          nullptr, nullptr, Y1);
    scatter_kernel<64, false><<<SCATTER_GRID, 256>>>(feats, T1, dTap31, dBase31, nt + 0,
                                                     p31, nullptr, nullptr, Y1);
    stats_kernel<<<STATS_GB, 256>>>(Y1, N, part);
    reduce1_kernel<<<64, 256>>>(part, STATS_GB, part2);
    reduce2_kernel<<<1, 128>>>(part2, invn, g0, b0, scaleA + 0, shiftA + 0);

    // ---- conv1_2 (1,3,3): BN0(lrelu(Y1)) -> Y2 (raw) ----
    center_kernel<128, true><<<nb, 256>>>(Y1, T12 + (size_t)4 * 128 * CO, N,
                                          scaleA + 0, shiftA + 0, Y2);
    scatter_kernel<128, true><<<SCATTER_GRID, 256>>>(Y1, T12, dTap13, dBase13, nt + 1,
                                                     p13, scaleA + 0, shiftA + 0, Y2);
    stats_kernel<<<STATS_GB, 256>>>(Y2, N, part);
    reduce1_kernel<<<64, 256>>>(part, STATS_GB, part2);
    reduce2_kernel<<<1, 128>>>(part2, invn, g0_2, b0_2, scaleA + 128, shiftA + 128);

    // ---- conv2 (1,3,3): feats -> Y3 (reuse Y1) ----
    center_kernel<64, false><<<nb, 256>>>(feats, T2 + (size_t)4 * 64 * CO, N,
                                          nullptr, nullptr, Y1);
    scatter_kernel<64, false><<<SCATTER_GRID, 256>>>(feats, T2, dTap13, dBase13, nt + 1,
                                                     p13, nullptr, nullptr, Y1);
    stats_kernel<<<STATS_GB, 256>>>(Y1, N, part);
    reduce1_kernel<<<64, 256>>>(part, STATS_GB, part2);
    reduce2_kernel<<<1, 128>>>(part2, invn, g1, b1, scaleA + 256, shiftA + 256);

    // ---- conv3 (3,1,3): BN2(lrelu(Y3)) -> Y4 (raw) ----
    center_kernel<128, true><<<nb, 256>>>(Y1, T3 + (size_t)4 * 128 * CO, N,
                                          scaleA + 256, shiftA + 256, Y4);
    scatter_kernel<128, true><<<SCATTER_GRID, 256>>>(Y1, T3, dTap31, dBase31, nt + 0,
                                                     p31, scaleA + 256, shiftA + 256, Y4);
    stats_kernel<<<STATS_GB, 256>>>(Y4, N, part);
    reduce1_kernel<<<64, 256>>>(part, STATS_GB, part2);
    reduce2_kernel<<<1, 128>>>(part2, invn, g2, b2, scaleA + 384, shiftA + 384);

    // ---- resA = BN3(lrelu(Y4)) + BN1(lrelu(Y2)) ----
    int n4 = N * (CO / 4);
    add_bn_kernel<<<(n4 + 255) / 256, 256>>>(Y4, Y2, scaleA + 384, shiftA + 384,
                                             scaleA + 128, shiftA + 128, resA, n4);

    // ---- pool conv (3,3,3)/(2,2,1): resA -> resB ----
    cudaMemsetAsync(resB, 0, (size_t)M * CO * sizeof(float));
    scatter_kernel<128, false><<<SCATTER_GRID, 256>>>(resA, Tp, dTapP, dBaseP, nt + 2,
                                                      pP, nullptr, nullptr, resB);
}

// round 10
// speedup vs baseline: 1.4942x; 1.0345x over previous
#include <cuda_runtime.h>
#include <cstdint>

// ---------------------------------------------------------------------------
// ResBlock sparse-conv, round 10: round-9 with the build_dir_all offset bug
// fixed (pool directory was written at +80000 but read at +40000).
//   - TF32 mma.sync GEMMs (round-8 proven)
//   - fused block-aggregated compaction (1-2 atomics per 512-thread block)
//   - merged pad + build_dir launches
// ---------------------------------------------------------------------------

constexpr int CO   = 128;
constexpr int TM   = 128;
constexpr int TKC  = 32;
constexpr int ASTR = 36;    // A row stride (words): conflict-free
constexpr int BSTR = 136;   // B row stride (words): conflict-free
constexpr int MAXN = 300000;
constexpr int STATS_GB = 2048;
constexpr int SCATTER_GRID = 296;

__device__ float g_Y1[(size_t)MAXN * CO];
__device__ float g_Y2[(size_t)MAXN * CO];
__device__ float g_Y4[(size_t)MAXN * CO];
__device__ float g_part[(size_t)STATS_GB * 256];
__device__ float g_part2[64 * 256];
__device__ float g_scale[4 * CO];
__device__ float g_shift[4 * CO];

__device__ int2 g_pairs31[(size_t)9 * MAXN];
__device__ int2 g_pairs13[(size_t)9 * MAXN];
__device__ int2 g_pairsP[(size_t)27 * MAXN];
__device__ int  g_cnt[64];          // 0..8: map31, 16..24: map13, 32..58: pool
__device__ int  g_dirTap[110000];
__device__ int  g_dirBase[110000];
__device__ int  g_nt[4];
__device__ uint32_t g_Wt[884736];   // all weights, tf32-rounded bits

// ---------------- helpers ----------------
__device__ __forceinline__ uint32_t tf32r(float x) {
    uint32_t u;
    asm("cvt.rna.tf32.f32 %0, %1;" : "=r"(u) : "f"(x));
    return u;
}
__device__ __forceinline__ void mma16n8k8(float* c, const uint32_t* a, const uint32_t* b) {
    asm volatile("mma.sync.aligned.m16n8k8.row.col.f32.tf32.tf32.f32 "
                 "{%0,%1,%2,%3}, {%4,%5,%6,%7}, {%8,%9}, {%0,%1,%2,%3};"
                 : "+f"(c[0]), "+f"(c[1]), "+f"(c[2]), "+f"(c[3])
                 : "r"(a[0]), "r"(a[1]), "r"(a[2]), "r"(a[3]), "r"(b[0]), "r"(b[1]));
}
__device__ __forceinline__ void redadd2(float* p, float a, float b) {
    asm volatile("red.global.add.v2.f32 [%0], {%1,%2};"
                 :: "l"(p), "f"(a), "f"(b) : "memory");
}
__device__ __forceinline__ float lrelu(float x) { return (x >= 0.f) ? x : 0.01f * x; }

// ---------------------------------------------------------------------------
// Weight pre-conversion, single launch over all 5 tensors.
// ---------------------------------------------------------------------------
__global__ void cvtw_all(const float* __restrict__ w1, const float* __restrict__ w12,
                         const float* __restrict__ w2, const float* __restrict__ w3,
                         const float* __restrict__ wp, uint32_t* __restrict__ out) {
    int i = blockIdx.x * 256 + threadIdx.x;
    if (i >= 221184) return;
    const float* src;
    int off;
    if      (i < 18432)  { src = w1;  off = 0; }
    else if (i < 55296)  { src = w12; off = 18432; }
    else if (i < 73728)  { src = w2;  off = 55296; }
    else if (i < 110592) { src = w3;  off = 73728; }
    else                 { src = wp;  off = 110592; }
    float4 v = __ldg((const float4*)src + (i - off));
    uint4 q;
    q.x = tf32r(v.x); q.y = tf32r(v.y); q.z = tf32r(v.z); q.w = tf32r(v.w);
    ((uint4*)out)[i] = q;
}

// ---------------------------------------------------------------------------
// Fused block-aggregated compaction: all three maps, 1-2 atomics per block.
// key = global index into cnt[64]. Segments are >=90k long so a 32-lane warp
// spans at most 2 distinct keys; a 512-thread block holds <=32 warp-groups.
// ---------------------------------------------------------------------------
__global__ void compact_fused(const int* __restrict__ map31, const int* __restrict__ map13,
                              const int* __restrict__ mpool, int N, int M,
                              int2* __restrict__ p31, int2* __restrict__ p13,
                              int2* __restrict__ pP, int* __restrict__ cnt) {
    const int tid  = threadIdx.x;
    const int lane = tid & 31, wid = tid >> 5;
    long long gi = (long long)blockIdx.x * 512 + tid;
    const long long n1 = 9LL * N, n2 = 18LL * N, n3 = n2 + 27LL * M;

    int key = 63, outIdx = 0, idx = -1;
    if (gi < n1) {
        int i = (int)gi;
        int k = i / N;
        outIdx = i - k * N;
        if (k != 4) idx = __ldg(&map31[i]);
        key = k;
    } else if (gi < n2) {
        int i = (int)(gi - n1);
        int k = i / N;
        outIdx = i - k * N;
        if (k != 4) idx = __ldg(&map13[i]);
        key = 16 + k;
    } else if (gi < n3) {
        int i = (int)(gi - n2);
        int k = i / M;
        outIdx = i - k * M;
        idx = __ldg(&mpool[i]);
        key = 32 + k;
    }
    const bool valid = (idx >= 0);

    unsigned samek  = __match_any_sync(0xffffffffu, key);
    unsigned voters = samek & __ballot_sync(0xffffffffu, valid);
    int leader = __ffs(voters) - 1;                     // valid lanes only use this
    bool isLeader = valid && (lane == leader);
    unsigned gl = __ballot_sync(0xffffffffu, isLeader); // leaders within this warp

    __shared__ int eKey[32], eCnt[32], eBase[32];
    if (tid < 32) eKey[tid] = -1;
    __syncthreads();

    int slot = -1;
    if (valid) {
        slot = wid * 2 + __popc(gl & ((1u << leader) - 1u));
        if (isLeader) { eKey[slot] = key; eCnt[slot] = __popc(voters); }
    }
    __syncthreads();

    if (tid == 0) {
#pragma unroll 1
        for (int e = 0; e < 32; ++e) {
            int k = eKey[e];
            if (k < 0) continue;
            bool first = true;
            for (int f = 0; f < e; ++f)
                if (eKey[f] == k) { first = false; break; }
            if (!first) continue;
            int tot = 0;
            for (int f = e; f < 32; ++f)
                if (eKey[f] == k) tot += eCnt[f];
            int b = atomicAdd(&cnt[k], tot);
            for (int f = e; f < 32; ++f)
                if (eKey[f] == k) { eBase[f] = b; b += eCnt[f]; }
        }
    }
    __syncthreads();

    if (valid) {
        int rank = __popc(voters & ((1u << lane) - 1u));
        int base = eBase[slot] + rank;
        if (key < 16)       p31[(size_t)key * N + base]        = make_int2(outIdx, idx);
        else if (key < 32)  p13[(size_t)(key - 16) * N + base] = make_int2(outIdx, idx);
        else                pP[(size_t)(key - 32) * M + base]  = make_int2(outIdx, idx);
    }
}

// One launch pads all three pair arrays to a multiple of TM.
__global__ void pad_all(const int* __restrict__ cnt, int N, int M,
                        int2* __restrict__ p31, int2* __restrict__ p13,
                        int2* __restrict__ pP) {
    int b = blockIdx.x;                  // 0..8: p31, 9..17: p13, 18..44: pP
    int2* pairs; int c;
    if (b < 9)       { c = cnt[b];           pairs = p31 + (size_t)b * N; }
    else if (b < 18) { c = cnt[16 + b - 9];  pairs = p13 + (size_t)(b - 9) * N; }
    else             { c = cnt[32 + b - 18]; pairs = pP  + (size_t)(b - 18) * M; }
    int e = ((c + TM - 1) / TM) * TM;
    for (int j = c + threadIdx.x; j < e; j += blockDim.x)
        pairs[j] = make_int2(-1, 0);
}

// One launch builds all three tile directories (blockIdx selects map).
__global__ void build_dir_all(const int* __restrict__ cnt, int N, int M,
                              int* __restrict__ dTap, int* __restrict__ dBase,
                              int* __restrict__ ntOut) {
    int which = blockIdx.x;              // 0: map31, 1: map13, 2: pool
    const int* c = cnt + (which == 0 ? 0 : which == 1 ? 16 : 32);
    int K   = which == 2 ? 27 : 9;
    int cap = which == 2 ? M : N;
    int* tileTap  = dTap  + which * 20000;   // 0 / 20000 / 40000  (FIXED)
    int* tileBase = dBase + which * 20000;
    __shared__ int ntk[32], off[32];
    if (threadIdx.x == 0) {
        int t = 0;
        for (int k = 0; k < K; ++k) {
            off[k] = t;
            ntk[k] = (c[k] + TM - 1) / TM;
            t += ntk[k];
        }
        ntOut[which] = t;
    }
    __syncthreads();
    for (int k = 0; k < K; ++k)
        for (int j = threadIdx.x; j < ntk[k]; j += blockDim.x) {
            tileTap[off[k] + j]  = k;
            tileBase[off[k] + j] = k * cap + j * TM;
        }
}

// ---------------------------------------------------------------------------
// MMA core: warp computes 64x32 of the 128x128 tile over a TK=32 chunk.
// ---------------------------------------------------------------------------
__device__ __forceinline__ void core_compute(float (*acc)[4][4],
                                             const uint32_t* __restrict__ As,
                                             const uint32_t* __restrict__ Bs,
                                             int mb, int nb, int lane) {
    const int l3 = lane & 3, l2 = lane >> 2;
#pragma unroll
    for (int ks = 0; ks < TKC; ks += 8) {
        uint32_t bf[4][2];
#pragma unroll
        for (int na = 0; na < 4; ++na) {
            bf[na][0] = Bs[(ks + l3) * BSTR + nb + na * 8 + l2];
            bf[na][1] = Bs[(ks + 4 + l3) * BSTR + nb + na * 8 + l2];
        }
#pragma unroll
        for (int ma = 0; ma < 4; ++ma) {
            const int mrow = mb + ma * 16 + l2;
            uint32_t af[4];
            af[0] = As[mrow * ASTR + ks + l3];
            af[1] = As[(mrow + 8) * ASTR + ks + l3];
            af[2] = As[mrow * ASTR + ks + 4 + l3];
            af[3] = As[(mrow + 8) * ASTR + ks + 4 + l3];
#pragma unroll
            for (int na = 0; na < 4; ++na) mma16n8k8(acc[ma][na], af, bf[na]);
        }
    }
}

// ---------------------------------------------------------------------------
// Dense center-tap GEMM: Out[m] = T(Fin[m]) @ Wc   (T = lrelu+BN if FUSE)
// ---------------------------------------------------------------------------
template<int CIN, bool FUSE>
__global__ void __launch_bounds__(256, 2) center_kernel(
    const float* __restrict__ Fin, const uint32_t* __restrict__ Wt, int M,
    const float* __restrict__ inScale, const float* __restrict__ inShift,
    float* __restrict__ Out)
{
    __shared__ uint32_t As[TM * ASTR];
    __shared__ uint32_t Bs[TKC * BSTR];
    __shared__ float sSc[128], sSh[128];

    const int tid  = threadIdx.x;
    const int m0   = blockIdx.x * TM;
    const int wid  = tid >> 5, lane = tid & 31;
    const int mb   = (wid & 1) * 64, nb = (wid >> 1) * 32;
    const int row  = tid >> 1, half = tid & 1;
    constexpr int CHUNKS = CIN / TKC;

    if (FUSE && tid < CIN) { sSc[tid] = inScale[tid]; sSh[tid] = inShift[tid]; }
    __syncthreads();

    float acc[4][4][4];
#pragma unroll
    for (int ma = 0; ma < 4; ++ma)
#pragma unroll
        for (int na = 0; na < 4; ++na)
#pragma unroll
            for (int p = 0; p < 4; ++p) acc[ma][na][p] = 0.f;

    const int m = m0 + row;
    float4 va[4];

    // prefetch chunk 0
    {
#pragma unroll
        for (int j = 0; j < 4; ++j) {
            float4 v = make_float4(0.f, 0.f, 0.f, 0.f);
            if (m < M) {
                v = __ldg((const float4*)(Fin + (size_t)m * CIN + half * 16) + j);
                if (FUSE) {
                    int c = half * 16 + j * 4;
                    v.x = fmaf(lrelu(v.x), sSc[c + 0], sSh[c + 0]);
                    v.y = fmaf(lrelu(v.y), sSc[c + 1], sSh[c + 1]);
                    v.z = fmaf(lrelu(v.z), sSc[c + 2], sSh[c + 2]);
                    v.w = fmaf(lrelu(v.w), sSc[c + 3], sSh[c + 3]);
                }
            }
            va[j] = v;
        }
    }

#pragma unroll 1
    for (int c = 0; c < CHUNKS; ++c) {
        const int c0 = c * TKC;
        __syncthreads();
#pragma unroll
        for (int j = 0; j < 4; ++j) {
            uint4 q;
            q.x = tf32r(va[j].x); q.y = tf32r(va[j].y);
            q.z = tf32r(va[j].z); q.w = tf32r(va[j].w);
            *(uint4*)&As[row * ASTR + half * 16 + j * 4] = q;
        }
#pragma unroll
        for (int j = 0; j < 4; ++j) {
            int i2 = tid + j * 256;
            int kk = i2 >> 5, c4 = (i2 & 31) << 2;
            uint4 b = __ldg((const uint4*)(Wt + (size_t)(c0 + kk) * CO + c4));
            *(uint4*)&Bs[kk * BSTR + c4] = b;
        }
        __syncthreads();
        if (c + 1 < CHUNKS) {
            const int cn = c0 + TKC;
#pragma unroll
            for (int j = 0; j < 4; ++j) {
                float4 v = make_float4(0.f, 0.f, 0.f, 0.f);
                if (m < M) {
                    v = __ldg((const float4*)(Fin + (size_t)m * CIN + cn + half * 16) + j);
                    if (FUSE) {
                        int cc = cn + half * 16 + j * 4;
                        v.x = fmaf(lrelu(v.x), sSc[cc + 0], sSh[cc + 0]);
                        v.y = fmaf(lrelu(v.y), sSc[cc + 1], sSh[cc + 1]);
                        v.z = fmaf(lrelu(v.z), sSc[cc + 2], sSh[cc + 2]);
                        v.w = fmaf(lrelu(v.w), sSc[cc + 3], sSh[cc + 3]);
                    }
                }
                va[j] = v;
            }
        }
        core_compute(acc, As, Bs, mb, nb, lane);
    }

    const int l3 = lane & 3, l2 = lane >> 2;
#pragma unroll
    for (int ma = 0; ma < 4; ++ma) {
        int r0 = m0 + mb + ma * 16 + l2;
        int r1 = r0 + 8;
#pragma unroll
        for (int na = 0; na < 4; ++na) {
            int col = nb + na * 8 + 2 * l3;
            if (r0 < M)
                *(float2*)&Out[(size_t)r0 * CO + col] = make_float2(acc[ma][na][0], acc[ma][na][1]);
            if (r1 < M)
                *(float2*)&Out[(size_t)r1 * CO + col] = make_float2(acc[ma][na][2], acc[ma][na][3]);
        }
    }
}

// ---------------------------------------------------------------------------
// Scatter-GEMM over compacted tap tiles; epilogue = red.global.add.v2.f32
// ---------------------------------------------------------------------------
template<int CIN, bool FUSE>
__global__ void __launch_bounds__(256, 2) scatter_kernel(
    const float* __restrict__ Fin, const uint32_t* __restrict__ Wt,
    const int* __restrict__ tileTap, const int* __restrict__ tileBase,
    const int* __restrict__ ntPtr, const int2* __restrict__ pairs,
    const float* __restrict__ inScale, const float* __restrict__ inShift,
    float* __restrict__ Out)
{
    __shared__ uint32_t As[TM * ASTR];
    __shared__ uint32_t Bs[TKC * BSTR];
    __shared__ int   sM[TM], sI[TM];
    __shared__ float sSc[128], sSh[128];

    const int tid  = threadIdx.x;
    const int wid  = tid >> 5, lane = tid & 31;
    const int mb   = (wid & 1) * 64, nb = (wid >> 1) * 32;
    const int row  = tid >> 1, half = tid & 1;
    const int l3   = lane & 3, l2 = lane >> 2;
    constexpr int CHUNKS = CIN / TKC;

    if (FUSE && tid < CIN) { sSc[tid] = inScale[tid]; sSh[tid] = inShift[tid]; }
    const int nTiles = __ldg(ntPtr);

    for (int t = blockIdx.x; t < nTiles; t += gridDim.x) {
        __syncthreads();
        const int k    = __ldg(&tileTap[t]);
        const int base = __ldg(&tileBase[t]);
        if (tid < TM) {
            int2 pr = __ldg(&pairs[(size_t)base + tid]);
            sM[tid] = pr.x;
            sI[tid] = pr.y;
        }
        __syncthreads();
        const uint32_t* Wk = Wt + (size_t)k * CIN * CO;
        const int idx = sI[row];

        float acc[4][4][4];
#pragma unroll
        for (int ma = 0; ma < 4; ++ma)
#pragma unroll
            for (int na = 0; na < 4; ++na)
#pragma unroll
                for (int p = 0; p < 4; ++p) acc[ma][na][p] = 0.f;

        float4 va[4];
#pragma unroll
        for (int j = 0; j < 4; ++j) {
            float4 v = __ldg((const float4*)(Fin + (size_t)idx * CIN + half * 16) + j);
            if (FUSE) {
                int cc = half * 16 + j * 4;
                v.x = fmaf(lrelu(v.x), sSc[cc + 0], sSh[cc + 0]);
                v.y = fmaf(lrelu(v.y), sSc[cc + 1], sSh[cc + 1]);
                v.z = fmaf(lrelu(v.z), sSc[cc + 2], sSh[cc + 2]);
                v.w = fmaf(lrelu(v.w), sSc[cc + 3], sSh[cc + 3]);
            }
            va[j] = v;
        }

#pragma unroll 1
        for (int c = 0; c < CHUNKS; ++c) {
            const int c0 = c * TKC;
            __syncthreads();
#pragma unroll
            for (int j = 0; j < 4; ++j) {
                uint4 q;
                q.x = tf32r(va[j].x); q.y = tf32r(va[j].y);
                q.z = tf32r(va[j].z); q.w = tf32r(va[j].w);
                *(uint4*)&As[row * ASTR + half * 16 + j * 4] = q;
            }
#pragma unroll
            for (int j = 0; j < 4; ++j) {
                int i2 = tid + j * 256;
                int kk = i2 >> 5, c4 = (i2 & 31) << 2;
                uint4 b = __ldg((const uint4*)(Wk + (size_t)(c0 + kk) * CO + c4));
                *(uint4*)&Bs[kk * BSTR + c4] = b;
            }
            __syncthreads();
            if (c + 1 < CHUNKS) {
                const int cn = c0 + TKC;
#pragma unroll
                for (int j = 0; j < 4; ++j) {
                    float4 v = __ldg((const float4*)(Fin + (size_t)idx * CIN + cn + half * 16) + j);
                    if (FUSE) {
                        int cc = cn + half * 16 + j * 4;
                        v.x = fmaf(lrelu(v.x), sSc[cc + 0], sSh[cc + 0]);
                        v.y = fmaf(lrelu(v.y), sSc[cc + 1], sSh[cc + 1]);
                        v.z = fmaf(lrelu(v.z), sSc[cc + 2], sSh[cc + 2]);
                        v.w = fmaf(lrelu(v.w), sSc[cc + 3], sSh[cc + 3]);
                    }
                    va[j] = v;
                }
            }
            core_compute(acc, As, Bs, mb, nb, lane);
        }

#pragma unroll
        for (int ma = 0; ma < 4; ++ma) {
            int lr0 = mb + ma * 16 + l2;
            int m0r = sM[lr0];
            int m1r = sM[lr0 + 8];
#pragma unroll
            for (int na = 0; na < 4; ++na) {
                int col = nb + na * 8 + 2 * l3;
                if (m0r >= 0) redadd2(Out + (size_t)m0r * CO + col, acc[ma][na][0], acc[ma][na][1]);
                if (m1r >= 0) redadd2(Out + (size_t)m1r * CO + col, acc[ma][na][2], acc[ma][na][3]);
            }
        }
    }
}

// ---------------------------------------------------------------------------
// BN stats on raw conv output (applies lrelu)
// ---------------------------------------------------------------------------
__global__ void stats_kernel(const float* __restrict__ Y, int N, float* __restrict__ part) {
    int c    = threadIdx.x & 127;
    int half = threadIdx.x >> 7;
    int rows = (N + gridDim.x - 1) / gridDim.x;
    int r0   = blockIdx.x * rows;
    int r1   = min(N, r0 + rows);
    float s = 0.f, q = 0.f;
    for (int r = r0 + half; r < r1; r += 2) {
        float x = lrelu(__ldg(&Y[(size_t)r * 128 + c]));
        s += x; q += x * x;
    }
    __shared__ float sh[256];
    sh[threadIdx.x] = s; __syncthreads();
    if (half == 0) part[(size_t)blockIdx.x * 256 + c] = sh[c] + sh[128 + c];
    __syncthreads();
    sh[threadIdx.x] = q; __syncthreads();
    if (half == 0) part[(size_t)blockIdx.x * 256 + 128 + c] = sh[c] + sh[128 + c];
}

__global__ void reduce1_kernel(const float* __restrict__ part, int nb,
                               float* __restrict__ part2) {
    int rpb = (nb + 63) >> 6;
    int r0  = blockIdx.x * rpb;
    int r1  = min(nb, r0 + rpb);
    float s = 0.f;
    for (int r = r0; r < r1; ++r) s += part[(size_t)r * 256 + threadIdx.x];
    part2[blockIdx.x * 256 + threadIdx.x] = s;
}

__global__ void reduce2_kernel(const float* __restrict__ part2, float invn,
                               const float* __restrict__ g, const float* __restrict__ b,
                               float* __restrict__ scale, float* __restrict__ shift) {
    int c = threadIdx.x;
    float s = 0.f, q = 0.f;
#pragma unroll
    for (int j = 0; j < 64; ++j) {
        s += part2[j * 256 + c];
        q += part2[j * 256 + 128 + c];
    }
    float mean = s * invn;
    float var  = q * invn - mean * mean;
    float sc   = g[c] * rsqrtf(var + 1e-5f);
    scale[c] = sc;
    shift[c] = b[c] - mean * sc;
}

__global__ void add_bn_kernel(const float* __restrict__ y4, const float* __restrict__ y2,
                              const float* __restrict__ sc4, const float* __restrict__ sh4,
                              const float* __restrict__ sc2, const float* __restrict__ sh2,
                              float* __restrict__ out, int n4) {
    int i = blockIdx.x * blockDim.x + threadIdx.x;
    if (i >= n4) return;
    int cg = i & 31;
    float4 a  = __ldg((const float4*)y4 + i);
    float4 c  = __ldg((const float4*)y2 + i);
    float4 s4 = __ldg((const float4*)sc4 + cg);
    float4 h4 = __ldg((const float4*)sh4 + cg);
    float4 s2 = __ldg((const float4*)sc2 + cg);
    float4 h2 = __ldg((const float4*)sh2 + cg);
    float4 o;
    o.x = fmaf(lrelu(a.x), s4.x, h4.x) + fmaf(lrelu(c.x), s2.x, h2.x);
    o.y = fmaf(lrelu(a.y), s4.y, h4.y) + fmaf(lrelu(c.y), s2.y, h2.y);
    o.z = fmaf(lrelu(a.z), s4.z, h4.z) + fmaf(lrelu(c.z), s2.z, h2.z);
    o.w = fmaf(lrelu(a.w), s4.w, h4.w) + fmaf(lrelu(c.w), s2.w, h2.w);
    ((float4*)out)[i] = o;
}

extern "C" void kernel_launch(void* const* d_in, const int* in_sizes, int n_in,
                              void* d_out, int out_size) {
    const float* feats = (const float*)d_in[0];
    const int*   map31 = (const int*)d_in[1];
    const int*   map13 = (const int*)d_in[2];
    const int*   mpool = (const int*)d_in[3];
    const float* W1    = (const float*)d_in[4];
    const float* W1_2  = (const float*)d_in[5];
    const float* W2    = (const float*)d_in[6];
    const float* W3    = (const float*)d_in[7];
    const float* Wp    = (const float*)d_in[8];
    const float* g0    = (const float*)d_in[9];
    const float* b0    = (const float*)d_in[10];
    const float* g0_2  = (const float*)d_in[11];
    const float* b0_2  = (const float*)d_in[12];
    const float* g1    = (const float*)d_in[13];
    const float* b1    = (const float*)d_in[14];
    const float* g2    = (const float*)d_in[15];
    const float* b2    = (const float*)d_in[16];

    int N = in_sizes[0] / 64;
    int M = in_sizes[3] / 27;

    float *Y1, *Y2, *Y4, *part, *part2, *scaleA, *shiftA;
    int2 *p31, *p13, *pP;
    int  *cnt, *dTap, *dBase, *nt;
    uint32_t* Wt;
    cudaGetSymbolAddress((void**)&Y1, g_Y1);
    cudaGetSymbolAddress((void**)&Y2, g_Y2);
    cudaGetSymbolAddress((void**)&Y4, g_Y4);
    cudaGetSymbolAddress((void**)&part, g_part);
    cudaGetSymbolAddress((void**)&part2, g_part2);
    cudaGetSymbolAddress((void**)&scaleA, g_scale);
    cudaGetSymbolAddress((void**)&shiftA, g_shift);
    cudaGetSymbolAddress((void**)&p31, g_pairs31);
    cudaGetSymbolAddress((void**)&p13, g_pairs13);
    cudaGetSymbolAddress((void**)&pP,  g_pairsP);
    cudaGetSymbolAddress((void**)&cnt, g_cnt);
    cudaGetSymbolAddress((void**)&dTap, g_dirTap);
    cudaGetSymbolAddress((void**)&dBase, g_dirBase);
    cudaGetSymbolAddress((void**)&nt, g_nt);
    cudaGetSymbolAddress((void**)&Wt, g_Wt);

    float* resB = (float*)d_out;
    float* resA = (float*)d_out + (size_t)M * CO;

    int nb = (N + TM - 1) / TM;
    float invn = 1.0f / (float)N;

    int* dTap31 = dTap;          int* dBase31 = dBase;
    int* dTap13 = dTap + 20000;  int* dBase13 = dBase + 20000;
    int* dTapP  = dTap + 40000;  int* dBaseP  = dBase + 40000;

    // pre-converted weight regions (word offsets)
    uint32_t* T1  = Wt;
    uint32_t* T12 = Wt + 73728;
    uint32_t* T2  = Wt + 221184;
    uint32_t* T3  = Wt + 294912;
    uint32_t* Tp  = Wt + 442368;
    cvtw_all<<<(221184 + 255) / 256, 256>>>(W1, W1_2, W2, W3, Wp, Wt);

    // ---- one-time compaction (fused, block-aggregated atomics) ----
    cudaMemsetAsync(cnt, 0, 64 * sizeof(int));
    long long total = 18LL * N + 27LL * M;
    int cgrid = (int)((total + 511) / 512);
    compact_fused<<<cgrid, 512>>>(map31, map13, mpool, N, M, p31, p13, pP, cnt);
    pad_all<<<45, 128>>>(cnt, N, M, p31, p13, pP);
    build_dir_all<<<3, 256>>>(cnt, N, M, dTap, dBase, nt);

    // ---- conv1 (3,1,3): feats -> Y1 (raw) ----
    center_kernel<64, false><<<nb, 256>>>(feats, T1 + (size_t)4 * 64 * CO, N,
                                          nullptr, nullptr, Y1);
    scatter_kernel<64, false><<<SCATTER_GRID, 256>>>(feats, T1, dTap31, dBase31, nt + 0,
                                                     p31, nullptr, nullptr, Y1);
    stats_kernel<<<STATS_GB, 256>>>(Y1, N, part);
    reduce1_kernel<<<64, 256>>>(part, STATS_GB, part2);
    reduce2_kernel<<<1, 128>>>(part2, invn, g0, b0, scaleA + 0, shiftA + 0);

    // ---- conv1_2 (1,3,3): BN0(lrelu(Y1)) -> Y2 (raw) ----
    center_kernel<128, true><<<nb, 256>>>(Y1, T12 + (size_t)4 * 128 * CO, N,
                                          scaleA + 0, shiftA + 0, Y2);
    scatter_kernel<128, true><<<SCATTER_GRID, 256>>>(Y1, T12, dTap13, dBase13, nt + 1,
                                                     p13, scaleA + 0, shiftA + 0, Y2);
    stats_kernel<<<STATS_GB, 256>>>(Y2, N, part);
    reduce1_kernel<<<64, 256>>>(part, STATS_GB, part2);
    reduce2_kernel<<<1, 128>>>(part2, invn, g0_2, b0_2, scaleA + 128, shiftA + 128);

    // ---- conv2 (1,3,3): feats -> Y3 (reuse Y1) ----
    center_kernel<64, false><<<nb, 256>>>(feats, T2 + (size_t)4 * 64 * CO, N,
                                          nullptr, nullptr, Y1);
    scatter_kernel<64, false><<<SCATTER_GRID, 256>>>(feats, T2, dTap13, dBase13, nt + 1,
                                                     p13, nullptr, nullptr, Y1);
    stats_kernel<<<STATS_GB, 256>>>(Y1, N, part);
    reduce1_kernel<<<64, 256>>>(part, STATS_GB, part2);
    reduce2_kernel<<<1, 128>>>(part2, invn, g1, b1, scaleA + 256, shiftA + 256);

    // ---- conv3 (3,1,3): BN2(lrelu(Y3)) -> Y4 (raw) ----
    center_kernel<128, true><<<nb, 256>>>(Y1, T3 + (size_t)4 * 128 * CO, N,
                                          scaleA + 256, shiftA + 256, Y4);
    scatter_kernel<128, true><<<SCATTER_GRID, 256>>>(Y1, T3, dTap31, dBase31, nt + 0,
                                                     p31, scaleA + 256, shiftA + 256, Y4);
    stats_kernel<<<STATS_GB, 256>>>(Y4, N, part);
    reduce1_kernel<<<64, 256>>>(part, STATS_GB, part2);
    reduce2_kernel<<<1, 128>>>(part2, invn, g2, b2, scaleA + 384, shiftA + 384);

    // ---- resA = BN3(lrelu(Y4)) + BN1(lrelu(Y2)) ----
    int n4 = N * (CO / 4);
    add_bn_kernel<<<(n4 + 255) / 256, 256>>>(Y4, Y2, scaleA + 384, shiftA + 384,
                                             scaleA + 128, shiftA + 128, resA, n4);

    // ---- pool conv (3,3,3)/(2,2,1): resA -> resB ----
    cudaMemsetAsync(resB, 0, (size_t)M * CO * sizeof(float));
    scatter_kernel<128, false><<<SCATTER_GRID, 256>>>(resA, Tp, dTapP, dBaseP, nt + 2,
                                                      pP, nullptr, nullptr, resB);
}

// round 11
// speedup vs baseline: 1.7119x; 1.1457x over previous
#include <cuda_runtime.h>
#include <cuda_fp16.h>
#include <cstdint>

// ---------------------------------------------------------------------------
// ResBlock sparse-conv, round 11: fp16 m16n8k16 MMA core (same 10-bit mantissa
// as tf32, 2x MAC/instr, half the smem + B traffic). Pipeline unchanged:
//   fused block-aggregated compaction, dense center GEMM + scatter GEMM,
//   separate BN stats passes, lrelu+BN fused into consumer gathers.
// ---------------------------------------------------------------------------

constexpr int CO    = 128;
constexpr int TM    = 128;
constexpr int TKC   = 32;     // K floats per chunk (= 16 half2)
constexpr int ASTR2 = 20;     // A row stride in uint32 (half2): banks 20*l2+l3 distinct
constexpr int BSTR2 = 136;    // B k2-row stride in uint32: banks 8*l3+l2 distinct
constexpr int MAXN  = 300000;
constexpr int STATS_GB = 2048;
constexpr int SCATTER_GRID = 296;

__device__ float g_Y1[(size_t)MAXN * CO];
__device__ float g_Y2[(size_t)MAXN * CO];
__device__ float g_Y4[(size_t)MAXN * CO];
__device__ float g_part[(size_t)STATS_GB * 256];
__device__ float g_part2[64 * 256];
__device__ float g_scale[4 * CO];
__device__ float g_shift[4 * CO];

__device__ int2 g_pairs31[(size_t)9 * MAXN];
__device__ int2 g_pairs13[(size_t)9 * MAXN];
__device__ int2 g_pairsP[(size_t)27 * MAXN];
__device__ int  g_cnt[64];          // 0..8: map31, 16..24: map13, 32..58: pool
__device__ int  g_dirTap[110000];
__device__ int  g_dirBase[110000];
__device__ int  g_nt[4];
__device__ uint32_t g_Wt[442368];   // all weights as half2 (paired along cin)

// ---------------- helpers ----------------
__device__ __forceinline__ void mma16n8k16(float* c, const uint32_t* a, const uint32_t* b) {
    asm volatile("mma.sync.aligned.m16n8k16.row.col.f32.f16.f16.f32 "
                 "{%0,%1,%2,%3}, {%4,%5,%6,%7}, {%8,%9}, {%0,%1,%2,%3};"
                 : "+f"(c[0]), "+f"(c[1]), "+f"(c[2]), "+f"(c[3])
                 : "r"(a[0]), "r"(a[1]), "r"(a[2]), "r"(a[3]), "r"(b[0]), "r"(b[1]));
}
__device__ __forceinline__ void redadd2(float* p, float a, float b) {
    asm volatile("red.global.add.v2.f32 [%0], {%1,%2};"
                 :: "l"(p), "f"(a), "f"(b) : "memory");
}
__device__ __forceinline__ float lrelu(float x) { return (x >= 0.f) ? x : 0.01f * x; }
__device__ __forceinline__ uint32_t pk2(float lo, float hi) {
    __half2 h = __floats2half2_rn(lo, hi);   // lo -> .x (low half)
    return *(uint32_t*)&h;
}

// ---------------------------------------------------------------------------
// Weight pre-conversion: pack (cin 2c2, 2c2+1) into half2, all 5 tensors.
// uint regions: T1 [0,36864) T12 [36864,110592) T2 [110592,147456)
//               T3 [147456,221184) Tp [221184,442368)
// ---------------------------------------------------------------------------
__global__ void cvtw_all(const float* __restrict__ w1, const float* __restrict__ w12,
                         const float* __restrict__ w2, const float* __restrict__ w3,
                         const float* __restrict__ wp, uint32_t* __restrict__ out) {
    int i = blockIdx.x * 256 + threadIdx.x;
    if (i >= 442368) return;
    const float* src; int off, cin;
    if      (i < 36864)  { src = w1;  off = 0;      cin = 64;  }
    else if (i < 110592) { src = w12; off = 36864;  cin = 128; }
    else if (i < 147456) { src = w2;  off = 110592; cin = 64;  }
    else if (i < 221184) { src = w3;  off = 147456; cin = 128; }
    else                 { src = wp;  off = 221184; cin = 128; }
    int l = i - off;
    int perTap = (cin >> 1) * 128;
    int tap = l / perTap, rem = l - tap * perTap;
    int c2 = rem >> 7, n = rem & 127;
    const float* p = src + ((size_t)(tap * cin + 2 * c2)) * 128 + n;
    out[i] = pk2(__ldg(p), __ldg(p + 128));
}

// ---------------------------------------------------------------------------
// Fused block-aggregated compaction (round-10 proven)
// ---------------------------------------------------------------------------
__global__ void compact_fused(const int* __restrict__ map31, const int* __restrict__ map13,
                              const int* __restrict__ mpool, int N, int M,
                              int2* __restrict__ p31, int2* __restrict__ p13,
                              int2* __restrict__ pP, int* __restrict__ cnt) {
    const int tid  = threadIdx.x;
    const int lane = tid & 31, wid = tid >> 5;
    long long gi = (long long)blockIdx.x * 512 + tid;
    const long long n1 = 9LL * N, n2 = 18LL * N, n3 = n2 + 27LL * M;

    int key = 63, outIdx = 0, idx = -1;
    if (gi < n1) {
        int i = (int)gi;
        int k = i / N;
        outIdx = i - k * N;
        if (k != 4) idx = __ldg(&map31[i]);
        key = k;
    } else if (gi < n2) {
        int i = (int)(gi - n1);
        int k = i / N;
        outIdx = i - k * N;
        if (k != 4) idx = __ldg(&map13[i]);
        key = 16 + k;
    } else if (gi < n3) {
        int i = (int)(gi - n2);
        int k = i / M;
        outIdx = i - k * M;
        idx = __ldg(&mpool[i]);
        key = 32 + k;
    }
    const bool valid = (idx >= 0);

    unsigned samek  = __match_any_sync(0xffffffffu, key);
    unsigned voters = samek & __ballot_sync(0xffffffffu, valid);
    int leader = __ffs(voters) - 1;
    bool isLeader = valid && (lane == leader);
    unsigned gl = __ballot_sync(0xffffffffu, isLeader);

    __shared__ int eKey[32], eCnt[32], eBase[32];
    if (tid < 32) eKey[tid] = -1;
    __syncthreads();

    int slot = -1;
    if (valid) {
        slot = wid * 2 + __popc(gl & ((1u << leader) - 1u));
        if (isLeader) { eKey[slot] = key; eCnt[slot] = __popc(voters); }
    }
    __syncthreads();

    if (tid == 0) {
#pragma unroll 1
        for (int e = 0; e < 32; ++e) {
            int k = eKey[e];
            if (k < 0) continue;
            bool first = true;
            for (int f = 0; f < e; ++f)
                if (eKey[f] == k) { first = false; break; }
            if (!first) continue;
            int tot = 0;
            for (int f = e; f < 32; ++f)
                if (eKey[f] == k) tot += eCnt[f];
            int b = atomicAdd(&cnt[k], tot);
            for (int f = e; f < 32; ++f)
                if (eKey[f] == k) { eBase[f] = b; b += eCnt[f]; }
        }
    }
    __syncthreads();

    if (valid) {
        int rank = __popc(voters & ((1u << lane) - 1u));
        int base = eBase[slot] + rank;
        if (key < 16)       p31[(size_t)key * N + base]        = make_int2(outIdx, idx);
        else if (key < 32)  p13[(size_t)(key - 16) * N + base] = make_int2(outIdx, idx);
        else                pP[(size_t)(key - 32) * M + base]  = make_int2(outIdx, idx);
    }
}

__global__ void pad_all(const int* __restrict__ cnt, int N, int M,
                        int2* __restrict__ p31, int2* __restrict__ p13,
                        int2* __restrict__ pP) {
    int b = blockIdx.x;
    int2* pairs; int c;
    if (b < 9)       { c = cnt[b];           pairs = p31 + (size_t)b * N; }
    else if (b < 18) { c = cnt[16 + b - 9];  pairs = p13 + (size_t)(b - 9) * N; }
    else             { c = cnt[32 + b - 18]; pairs = pP  + (size_t)(b - 18) * M; }
    int e = ((c + TM - 1) / TM) * TM;
    for (int j = c + threadIdx.x; j < e; j += blockDim.x)
        pairs[j] = make_int2(-1, 0);
}

__global__ void build_dir_all(const int* __restrict__ cnt, int N, int M,
                              int* __restrict__ dTap, int* __restrict__ dBase,
                              int* __restrict__ ntOut) {
    int which = blockIdx.x;
    const int* c = cnt + (which == 0 ? 0 : which == 1 ? 16 : 32);
    int K   = which == 2 ? 27 : 9;
    int cap = which == 2 ? M : N;
    int* tileTap  = dTap  + which * 20000;
    int* tileBase = dBase + which * 20000;
    __shared__ int ntk[32], off[32];
    if (threadIdx.x == 0) {
        int t = 0;
        for (int k = 0; k < K; ++k) {
            off[k] = t;
            ntk[k] = (c[k] + TM - 1) / TM;
            t += ntk[k];
        }
        ntOut[which] = t;
    }
    __syncthreads();
    for (int k = 0; k < K; ++k)
        for (int j = threadIdx.x; j < ntk[k]; j += blockDim.x) {
            tileTap[off[k] + j]  = k;
            tileBase[off[k] + j] = k * cap + j * TM;
        }
}

// ---------------------------------------------------------------------------
// fp16 MMA core: warp computes 64x32 of the 128x128 tile over one TKC chunk
// (= 2 K-blocks of 16). As[m][k2] stride 20, Bs[k2][n] stride 136.
// ---------------------------------------------------------------------------
__device__ __forceinline__ void core16(float (*acc)[4][4],
                                       const uint32_t* __restrict__ As,
                                       const uint32_t* __restrict__ Bs,
                                       int mb, int nb, int lane) {
    const int l3 = lane & 3, l2 = lane >> 2;
#pragma unroll
    for (int kb = 0; kb < 2; ++kb) {
        const int ks2 = kb * 8;
        uint32_t bf[4][2];
#pragma unroll
        for (int na = 0; na < 4; ++na) {
            bf[na][0] = Bs[(ks2 + l3) * BSTR2 + nb + na * 8 + l2];
            bf[na][1] = Bs[(ks2 + 4 + l3) * BSTR2 + nb + na * 8 + l2];
        }
#pragma unroll
        for (int ma = 0; ma < 4; ++ma) {
            const int mrow = mb + ma * 16 + l2;
            uint32_t af[4];
            af[0] = As[mrow * ASTR2 + ks2 + l3];
            af[1] = As[(mrow + 8) * ASTR2 + ks2 + l3];
            af[2] = As[mrow * ASTR2 + ks2 + 4 + l3];
            af[3] = As[(mrow + 8) * ASTR2 + ks2 + 4 + l3];
#pragma unroll
            for (int na = 0; na < 4; ++na) mma16n8k16(acc[ma][na], af, bf[na]);
        }
    }
}

// ---------------------------------------------------------------------------
// Dense center-tap GEMM: Out[m] = T(Fin[m]) @ Wc   (T = lrelu+BN if FUSE)
// ---------------------------------------------------------------------------
template<int CIN, bool FUSE>
__global__ void __launch_bounds__(256, 2) center_kernel(
    const float* __restrict__ Fin, const uint32_t* __restrict__ Wt, int M,
    const float* __restrict__ inScale, const float* __restrict__ inShift,
    float* __restrict__ Out)
{
    __shared__ uint32_t As[TM * ASTR2];
    __shared__ uint32_t Bs[16 * BSTR2];
    __shared__ float sSc[128], sSh[128];

    const int tid  = threadIdx.x;
    const int m0   = blockIdx.x * TM;
    const int wid  = tid >> 5, lane = tid & 31;
    const int mb   = (wid & 1) * 64, nb = (wid >> 1) * 32;
    const int row  = tid >> 1, half = tid & 1;
    constexpr int CHUNKS = CIN / TKC;

    if (FUSE && tid < CIN) { sSc[tid] = inScale[tid]; sSh[tid] = inShift[tid]; }
    __syncthreads();

    float acc[4][4][4];
#pragma unroll
    for (int ma = 0; ma < 4; ++ma)
#pragma unroll
        for (int na = 0; na < 4; ++na)
#pragma unroll
            for (int p = 0; p < 4; ++p) acc[ma][na][p] = 0.f;

    const int m = m0 + row;
    float4 va[4];

    // prefetch chunk 0 (16 floats per thread: columns half*16 .. +15)
    {
#pragma unroll
        for (int j = 0; j < 4; ++j) {
            float4 v = make_float4(0.f, 0.f, 0.f, 0.f);
            if (m < M) {
                v = __ldg((const float4*)(Fin + (size_t)m * CIN + half * 16) + j);
                if (FUSE) {
                    int c = half * 16 + j * 4;
                    v.x = fmaf(lrelu(v.x), sSc[c + 0], sSh[c + 0]);
                    v.y = fmaf(lrelu(v.y), sSc[c + 1], sSh[c + 1]);
                    v.z = fmaf(lrelu(v.z), sSc[c + 2], sSh[c + 2]);
                    v.w = fmaf(lrelu(v.w), sSc[c + 3], sSh[c + 3]);
                }
            }
            va[j] = v;
        }
    }

#pragma unroll 1
    for (int c = 0; c < CHUNKS; ++c) {
        __syncthreads();
        // store A chunk as half2 (2 x uint4 per thread, conflict-free)
        {
            uint32_t q[8];
#pragma unroll
            for (int j = 0; j < 4; ++j) {
                q[2 * j]     = pk2(va[j].x, va[j].y);
                q[2 * j + 1] = pk2(va[j].z, va[j].w);
            }
            uint32_t* ap = &As[row * ASTR2 + half * 8];
            *(uint4*)ap       = make_uint4(q[0], q[1], q[2], q[3]);
            *(uint4*)(ap + 4) = make_uint4(q[4], q[5], q[6], q[7]);
        }
        // B chunk: copy pre-packed half2 weights (16 k2-rows x 128)
        {
            const int c02 = c * 16;
#pragma unroll
            for (int j = 0; j < 2; ++j) {
                int i2 = tid + j * 256;
                int kk2 = i2 >> 5, c4 = (i2 & 31) << 2;
                uint4 b = __ldg((const uint4*)(Wt + (size_t)(c02 + kk2) * CO + c4));
                *(uint4*)&Bs[kk2 * BSTR2 + c4] = b;
            }
        }
        __syncthreads();
        // prefetch next chunk (LDGs overlap MMA)
        if (c + 1 < CHUNKS) {
            const int cn = (c + 1) * TKC;
#pragma unroll
            for (int j = 0; j < 4; ++j) {
                float4 v = make_float4(0.f, 0.f, 0.f, 0.f);
                if (m < M) {
                    v = __ldg((const float4*)(Fin + (size_t)m * CIN + cn + half * 16) + j);
                    if (FUSE) {
                        int cc = cn + half * 16 + j * 4;
                        v.x = fmaf(lrelu(v.x), sSc[cc + 0], sSh[cc + 0]);
                        v.y = fmaf(lrelu(v.y), sSc[cc + 1], sSh[cc + 1]);
                        v.z = fmaf(lrelu(v.z), sSc[cc + 2], sSh[cc + 2]);
                        v.w = fmaf(lrelu(v.w), sSc[cc + 3], sSh[cc + 3]);
                    }
                }
                va[j] = v;
            }
        }
        core16(acc, As, Bs, mb, nb, lane);
    }

    const int l3 = lane & 3, l2 = lane >> 2;
#pragma unroll
    for (int ma = 0; ma < 4; ++ma) {
        int r0 = m0 + mb + ma * 16 + l2;
        int r1 = r0 + 8;
#pragma unroll
        for (int na = 0; na < 4; ++na) {
            int col = nb + na * 8 + 2 * l3;
            if (r0 < M)
                *(float2*)&Out[(size_t)r0 * CO + col] = make_float2(acc[ma][na][0], acc[ma][na][1]);
            if (r1 < M)
                *(float2*)&Out[(size_t)r1 * CO + col] = make_float2(acc[ma][na][2], acc[ma][na][3]);
        }
    }
}

// ---------------------------------------------------------------------------
// Scatter-GEMM over compacted tap tiles; epilogue = red.global.add.v2.f32
// ---------------------------------------------------------------------------
template<int CIN, bool FUSE>
__global__ void __launch_bounds__(256, 2) scatter_kernel(
    const float* __restrict__ Fin, const uint32_t* __restrict__ Wt,
    const int* __restrict__ tileTap, const int* __restrict__ tileBase,
    const int* __restrict__ ntPtr, const int2* __restrict__ pairs,
    const float* __restrict__ inScale, const float* __restrict__ inShift,
    float* __restrict__ Out)
{
    __shared__ uint32_t As[TM * ASTR2];
    __shared__ uint32_t Bs[16 * BSTR2];
    __shared__ int   sM[TM], sI[TM];
    __shared__ float sSc[128], sSh[128];

    const int tid  = threadIdx.x;
    const int wid  = tid >> 5, lane = tid & 31;
    const int mb   = (wid & 1) * 64, nb = (wid >> 1) * 32;
    const int row  = tid >> 1, half = tid & 1;
    const int l3   = lane & 3, l2 = lane >> 2;
    constexpr int CHUNKS = CIN / TKC;

    if (FUSE && tid < CIN) { sSc[tid] = inScale[tid]; sSh[tid] = inShift[tid]; }
    const int nTiles = __ldg(ntPtr);

    for (int t = blockIdx.x; t < nTiles; t += gridDim.x) {
        __syncthreads();
        const int k    = __ldg(&tileTap[t]);
        const int base = __ldg(&tileBase[t]);
        if (tid < TM) {
            int2 pr = __ldg(&pairs[(size_t)base + tid]);
            sM[tid] = pr.x;
            sI[tid] = pr.y;
        }
        __syncthreads();
        const uint32_t* Wk = Wt + (size_t)k * (CIN / 2) * CO;
        const int idx = sI[row];

        float acc[4][4][4];
#pragma unroll
        for (int ma = 0; ma < 4; ++ma)
#pragma unroll
            for (int na = 0; na < 4; ++na)
#pragma unroll
                for (int p = 0; p < 4; ++p) acc[ma][na][p] = 0.f;

        float4 va[4];
#pragma unroll
        for (int j = 0; j < 4; ++j) {
            float4 v = __ldg((const float4*)(Fin + (size_t)idx * CIN + half * 16) + j);
            if (FUSE) {
                int cc = half * 16 + j * 4;
                v.x = fmaf(lrelu(v.x), sSc[cc + 0], sSh[cc + 0]);
                v.y = fmaf(lrelu(v.y), sSc[cc + 1], sSh[cc + 1]);
                v.z = fmaf(lrelu(v.z), sSc[cc + 2], sSh[cc + 2]);
                v.w = fmaf(lrelu(v.w), sSc[cc + 3], sSh[cc + 3]);
            }
            va[j] = v;
        }

#pragma unroll 1
        for (int c = 0; c < CHUNKS; ++c) {
            __syncthreads();
            {
                uint32_t q[8];
#pragma unroll
                for (int j = 0; j < 4; ++j) {
                    q[2 * j]     = pk2(va[j].x, va[j].y);
                    q[2 * j + 1] = pk2(va[j].z, va[j].w);
                }
                uint32_t* ap = &As[row * ASTR2 + half * 8];
                *(uint4*)ap       = make_uint4(q[0], q[1], q[2], q[3]);
                *(uint4*)(ap + 4) = make_uint4(q[4], q[5], q[6], q[7]);
            }
            {
                const int c02 = c * 16;
#pragma unroll
                for (int j = 0; j < 2; ++j) {
                    int i2 = tid + j * 256;
                    int kk2 = i2 >> 5, c4 = (i2 & 31) << 2;
                    uint4 b = __ldg((const uint4*)(Wk + (size_t)(c02 + kk2) * CO + c4));
                    *(uint4*)&Bs[kk2 * BSTR2 + c4] = b;
                }
            }
            __syncthreads();
            if (c + 1 < CHUNKS) {
                const int cn = (c + 1) * TKC;
#pragma unroll
                for (int j = 0; j < 4; ++j) {
                    float4 v = __ldg((const float4*)(Fin + (size_t)idx * CIN + cn + half * 16) + j);
                    if (FUSE) {
                        int cc = cn + half * 16 + j * 4;
                        v.x = fmaf(lrelu(v.x), sSc[cc + 0], sSh[cc + 0]);
                        v.y = fmaf(lrelu(v.y), sSc[cc + 1], sSh[cc + 1]);
                        v.z = fmaf(lrelu(v.z), sSc[cc + 2], sSh[cc + 2]);
                        v.w = fmaf(lrelu(v.w), sSc[cc + 3], sSh[cc + 3]);
                    }
                    va[j] = v;
                }
            }
            core16(acc, As, Bs, mb, nb, lane);
        }

#pragma unroll
        for (int ma = 0; ma < 4; ++ma) {
            int lr0 = mb + ma * 16 + l2;
            int m0r = sM[lr0];
            int m1r = sM[lr0 + 8];
#pragma unroll
            for (int na = 0; na < 4; ++na) {
                int col = nb + na * 8 + 2 * l3;
                if (m0r >= 0) redadd2(Out + (size_t)m0r * CO + col, acc[ma][na][0], acc[ma][na][1]);
                if (m1r >= 0) redadd2(Out + (size_t)m1r * CO + col, acc[ma][na][2], acc[ma][na][3]);
            }
        }
    }
}

// ---------------------------------------------------------------------------
// BN stats on raw conv output (applies lrelu)
// ---------------------------------------------------------------------------
__global__ void stats_kernel(const float* __restrict__ Y, int N, float* __restrict__ part) {
    int c    = threadIdx.x & 127;
    int half = threadIdx.x >> 7;
    int rows = (N + gridDim.x - 1) / gridDim.x;
    int r0   = blockIdx.x * rows;
    int r1   = min(N, r0 + rows);
    float s = 0.f, q = 0.f;
    for (int r = r0 + half; r < r1; r += 2) {
        float x = lrelu(__ldg(&Y[(size_t)r * 128 + c]));
        s += x; q += x * x;
    }
    __shared__ float sh[256];
    sh[threadIdx.x] = s; __syncthreads();
    if (half == 0) part[(size_t)blockIdx.x * 256 + c] = sh[c] + sh[128 + c];
    __syncthreads();
    sh[threadIdx.x] = q; __syncthreads();
    if (half == 0) part[(size_t)blockIdx.x * 256 + 128 + c] = sh[c] + sh[128 + c];
}

__global__ void reduce1_kernel(const float* __restrict__ part, int nb,
                               float* __restrict__ part2) {
    int rpb = (nb + 63) >> 6;
    int r0  = blockIdx.x * rpb;
    int r1  = min(nb, r0 + rpb);
    float s = 0.f;
    for (int r = r0; r < r1; ++r) s += part[(size_t)r * 256 + threadIdx.x];
    part2[blockIdx.x * 256 + threadIdx.x] = s;
}

__global__ void reduce2_kernel(const float* __restrict__ part2, float invn,
                               const float* __restrict__ g, const float* __restrict__ b,
                               float* __restrict__ scale, float* __restrict__ shift) {
    int c = threadIdx.x;
    float s = 0.f, q = 0.f;
#pragma unroll
    for (int j = 0; j < 64; ++j) {
        s += part2[j * 256 + c];
        q += part2[j * 256 + 128 + c];
    }
    float mean = s * invn;
    float var  = q * invn - mean * mean;
    float sc   = g[c] * rsqrtf(var + 1e-5f);
    scale[c] = sc;
    shift[c] = b[c] - mean * sc;
}

__global__ void add_bn_kernel(const float* __restrict__ y4, const float* __restrict__ y2,
                              const float* __restrict__ sc4, const float* __restrict__ sh4,
                              const float* __restrict__ sc2, const float* __restrict__ sh2,
                              float* __restrict__ out, int n4) {
    int i = blockIdx.x * blockDim.x + threadIdx.x;
    if (i >= n4) return;
    int cg = i & 31;
    float4 a  = __ldg((const float4*)y4 + i);
    float4 c  = __ldg((const float4*)y2 + i);
    float4 s4 = __ldg((const float4*)sc4 + cg);
    float4 h4 = __ldg((const float4*)sh4 + cg);
    float4 s2 = __ldg((const float4*)sc2 + cg);
    float4 h2 = __ldg((const float4*)sh2 + cg);
    float4 o;
    o.x = fmaf(lrelu(a.x), s4.x, h4.x) + fmaf(lrelu(c.x), s2.x, h2.x);
    o.y = fmaf(lrelu(a.y), s4.y, h4.y) + fmaf(lrelu(c.y), s2.y, h2.y);
    o.z = fmaf(lrelu(a.z), s4.z, h4.z) + fmaf(lrelu(c.z), s2.z, h2.z);
    o.w = fmaf(lrelu(a.w), s4.w, h4.w) + fmaf(lrelu(c.w), s2.w, h2.w);
    ((float4*)out)[i] = o;
}

extern "C" void kernel_launch(void* const* d_in, const int* in_sizes, int n_in,
                              void* d_out, int out_size) {
    const float* feats = (const float*)d_in[0];
    const int*   map31 = (const int*)d_in[1];
    const int*   map13 = (const int*)d_in[2];
    const int*   mpool = (const int*)d_in[3];
    const float* W1    = (const float*)d_in[4];
    const float* W1_2  = (const float*)d_in[5];
    const float* W2    = (const float*)d_in[6];
    const float* W3    = (const float*)d_in[7];
    const float* Wp    = (const float*)d_in[8];
    const float* g0    = (const float*)d_in[9];
    const float* b0    = (const float*)d_in[10];
    const float* g0_2  = (const float*)d_in[11];
    const float* b0_2  = (const float*)d_in[12];
    const float* g1    = (const float*)d_in[13];
    const float* b1    = (const float*)d_in[14];
    const float* g2    = (const float*)d_in[15];
    const float* b2    = (const float*)d_in[16];

    int N = in_sizes[0] / 64;
    int M = in_sizes[3] / 27;

    float *Y1, *Y2, *Y4, *part, *part2, *scaleA, *shiftA;
    int2 *p31, *p13, *pP;
    int  *cnt, *dTap, *dBase, *nt;
    uint32_t* Wt;
    cudaGetSymbolAddress((void**)&Y1, g_Y1);
    cudaGetSymbolAddress((void**)&Y2, g_Y2);
    cudaGetSymbolAddress((void**)&Y4, g_Y4);
    cudaGetSymbolAddress((void**)&part, g_part);
    cudaGetSymbolAddress((void**)&part2, g_part2);
    cudaGetSymbolAddress((void**)&scaleA, g_scale);
    cudaGetSymbolAddress((void**)&shiftA, g_shift);
    cudaGetSymbolAddress((void**)&p31, g_pairs31);
    cudaGetSymbolAddress((void**)&p13, g_pairs13);
    cudaGetSymbolAddress((void**)&pP,  g_pairsP);
    cudaGetSymbolAddress((void**)&cnt, g_cnt);
    cudaGetSymbolAddress((void**)&dTap, g_dirTap);
    cudaGetSymbolAddress((void**)&dBase, g_dirBase);
    cudaGetSymbolAddress((void**)&nt, g_nt);
    cudaGetSymbolAddress((void**)&Wt, g_Wt);

    float* resB = (float*)d_out;
    float* resA = (float*)d_out + (size_t)M * CO;

    int nb = (N + TM - 1) / TM;
    float invn = 1.0f / (float)N;

    int* dTap31 = dTap;          int* dBase31 = dBase;
    int* dTap13 = dTap + 20000;  int* dBase13 = dBase + 20000;
    int* dTapP  = dTap + 40000;  int* dBaseP  = dBase + 40000;

    // packed half2 weight regions (uint offsets)
    uint32_t* T1  = Wt;
    uint32_t* T12 = Wt + 36864;
    uint32_t* T2  = Wt + 110592;
    uint32_t* T3  = Wt + 147456;
    uint32_t* Tp  = Wt + 221184;
    cvtw_all<<<(442368 + 255) / 256, 256>>>(W1, W1_2, W2, W3, Wp, Wt);

    // ---- one-time compaction (fused, block-aggregated atomics) ----
    cudaMemsetAsync(cnt, 0, 64 * sizeof(int));
    long long total = 18LL * N + 27LL * M;
    int cgrid = (int)((total + 511) / 512);
    compact_fused<<<cgrid, 512>>>(map31, map13, mpool, N, M, p31, p13, pP, cnt);
    pad_all<<<45, 128>>>(cnt, N, M, p31, p13, pP);
    build_dir_all<<<3, 256>>>(cnt, N, M, dTap, dBase, nt);

    // ---- conv1 (3,1,3): feats -> Y1 (raw) ----  center tap = 4
    center_kernel<64, false><<<nb, 256>>>(feats, T1 + (size_t)4 * 32 * CO, N,
                                          nullptr, nullptr, Y1);
    scatter_kernel<64, false><<<SCATTER_GRID, 256>>>(feats, T1, dTap31, dBase31, nt + 0,
                                                     p31, nullptr, nullptr, Y1);
    stats_kernel<<<STATS_GB, 256>>>(Y1, N, part);
    reduce1_kernel<<<64, 256>>>(part, STATS_GB, part2);
    reduce2_kernel<<<1, 128>>>(part2, invn, g0, b0, scaleA + 0, shiftA + 0);

    // ---- conv1_2 (1,3,3): BN0(lrelu(Y1)) -> Y2 (raw) ----
    center_kernel<128, true><<<nb, 256>>>(Y1, T12 + (size_t)4 * 64 * CO, N,
                                          scaleA + 0, shiftA + 0, Y2);
    scatter_kernel<128, true><<<SCATTER_GRID, 256>>>(Y1, T12, dTap13, dBase13, nt + 1,
                                                     p13, scaleA + 0, shiftA + 0, Y2);
    stats_kernel<<<STATS_GB, 256>>>(Y2, N, part);
    reduce1_kernel<<<64, 256>>>(part, STATS_GB, part2);
    reduce2_kernel<<<1, 128>>>(part2, invn, g0_2, b0_2, scaleA + 128, shiftA + 128);

    // ---- conv2 (1,3,3): feats -> Y3 (reuse Y1) ----
    center_kernel<64, false><<<nb, 256>>>(feats, T2 + (size_t)4 * 32 * CO, N,
                                          nullptr, nullptr, Y1);
    scatter_kernel<64, false><<<SCATTER_GRID, 256>>>(feats, T2, dTap13, dBase13, nt + 1,
                                                     p13, nullptr, nullptr, Y1);
    stats_kernel<<<STATS_GB, 256>>>(Y1, N, part);
    reduce1_kernel<<<64, 256>>>(part, STATS_GB, part2);
    reduce2_kernel<<<1, 128>>>(part2, invn, g1, b1, scaleA + 256, shiftA + 256);

    // ---- conv3 (3,1,3): BN2(lrelu(Y3)) -> Y4 (raw) ----
    center_kernel<128, true><<<nb, 256>>>(Y1, T3 + (size_t)4 * 64 * CO, N,
                                          scaleA + 256, shiftA + 256, Y4);
    scatter_kernel<128, true><<<SCATTER_GRID, 256>>>(Y1, T3, dTap31, dBase31, nt + 0,
                                                     p31, scaleA + 256, shiftA + 256, Y4);
    stats_kernel<<<STATS_GB, 256>>>(Y4, N, part);
    reduce1_kernel<<<64, 256>>>(part, STATS_GB, part2);
    reduce2_kernel<<<1, 128>>>(part2, invn, g2, b2, scaleA + 384, shiftA + 384);

    // ---- resA = BN3(lrelu(Y4)) + BN1(lrelu(Y2)) ----
    int n4 = N * (CO / 4);
    add_bn_kernel<<<(n4 + 255) / 256, 256>>>(Y4, Y2, scaleA + 384, shiftA + 384,
                                             scaleA + 128, shiftA + 128, resA, n4);

    // ---- pool conv (3,3,3)/(2,2,1): resA -> resB ----
    cudaMemsetAsync(resB, 0, (size_t)M * CO * sizeof(float));
    scatter_kernel<128, false><<<SCATTER_GRID, 256>>>(resA, Tp, dTapP, dBaseP, nt + 2,
                                                      pP, nullptr, nullptr, resB);
}

// round 12
// speedup vs baseline: 1.7492x; 1.0218x over previous
#include <cuda_runtime.h>
#include <cuda_fp16.h>
#include <cstdint>

// ---------------------------------------------------------------------------
// ResBlock sparse-conv, round 12: fp16 activations materialized once per
// tensor (transform passes fuse lrelu+BN+cvt); GEMM gathers are pure half2
// uint4 copies (half the bytes, zero per-gather math), TKC=64 (half the syncs).
// fp16 m16n8k16 MMA core; pipeline otherwise as round 11.
// ---------------------------------------------------------------------------

constexpr int CO    = 128;
constexpr int TM    = 128;
constexpr int ASTR2 = 36;     // A row stride in uint32: frag banks 4*l2+l3 distinct
constexpr int BSTR2 = 136;    // B k2-row stride in uint32: banks 8*l3+l2 distinct
constexpr int MAXN  = 300000;
constexpr int STATS_GB = 2048;
constexpr int SCATTER_GRID = 296;

__device__ float g_Y1[(size_t)MAXN * CO];
__device__ float g_Y2[(size_t)MAXN * CO];
__device__ float g_Y4[(size_t)MAXN * CO];
__device__ uint32_t g_F16[(size_t)MAXN * 32];   // feats as half2 (64ch)
__device__ uint32_t g_X16[(size_t)MAXN * 64];   // transformed acts as half2 (128ch)
__device__ float g_part[(size_t)STATS_GB * 256];
__device__ float g_part2[64 * 256];
__device__ float g_scale[4 * CO];
__device__ float g_shift[4 * CO];

__device__ int2 g_pairs31[(size_t)9 * MAXN];
__device__ int2 g_pairs13[(size_t)9 * MAXN];
__device__ int2 g_pairsP[(size_t)27 * MAXN];
__device__ int  g_cnt[64];
__device__ int  g_dirTap[110000];
__device__ int  g_dirBase[110000];
__device__ int  g_nt[4];
__device__ uint32_t g_Wt[442368];   // weights as half2 (paired along cin)

// ---------------- helpers ----------------
__device__ __forceinline__ void mma16n8k16(float* c, const uint32_t* a, const uint32_t* b) {
    asm volatile("mma.sync.aligned.m16n8k16.row.col.f32.f16.f16.f32 "
                 "{%0,%1,%2,%3}, {%4,%5,%6,%7}, {%8,%9}, {%0,%1,%2,%3};"
                 : "+f"(c[0]), "+f"(c[1]), "+f"(c[2]), "+f"(c[3])
                 : "r"(a[0]), "r"(a[1]), "r"(a[2]), "r"(a[3]), "r"(b[0]), "r"(b[1]));
}
__device__ __forceinline__ void redadd2(float* p, float a, float b) {
    asm volatile("red.global.add.v2.f32 [%0], {%1,%2};"
                 :: "l"(p), "f"(a), "f"(b) : "memory");
}
__device__ __forceinline__ float lrelu(float x) { return (x >= 0.f) ? x : 0.01f * x; }
__device__ __forceinline__ uint32_t pk2(float lo, float hi) {
    __half2 h = __floats2half2_rn(lo, hi);
    return *(uint32_t*)&h;
}

// ---------------------------------------------------------------------------
// Weight pre-conversion: pack (cin 2c2, 2c2+1) into half2, all 5 tensors.
// ---------------------------------------------------------------------------
__global__ void cvtw_all(const float* __restrict__ w1, const float* __restrict__ w12,
                         const float* __restrict__ w2, const float* __restrict__ w3,
                         const float* __restrict__ wp, uint32_t* __restrict__ out) {
    int i = blockIdx.x * 256 + threadIdx.x;
    if (i >= 442368) return;
    const float* src; int off, cin;
    if      (i < 36864)  { src = w1;  off = 0;      cin = 64;  }
    else if (i < 110592) { src = w12; off = 36864;  cin = 128; }
    else if (i < 147456) { src = w2;  off = 110592; cin = 64;  }
    else if (i < 221184) { src = w3;  off = 147456; cin = 128; }
    else                 { src = wp;  off = 221184; cin = 128; }
    int l = i - off;
    int perTap = (cin >> 1) * 128;
    int tap = l / perTap, rem = l - tap * perTap;
    int c2 = rem >> 7, n = rem & 127;
    const float* p = src + ((size_t)(tap * cin + 2 * c2)) * 128 + n;
    out[i] = pk2(__ldg(p), __ldg(p + 128));
}

// feats (64ch fp32) -> F16 half2
__global__ void cvt_feats(const float* __restrict__ F, int n4, uint32_t* __restrict__ out) {
    int i = blockIdx.x * 256 + threadIdx.x;
    if (i >= n4) return;
    float4 v = __ldg((const float4*)F + i);
    ((uint2*)out)[i] = make_uint2(pk2(v.x, v.y), pk2(v.z, v.w));
}

// Y (128ch fp32 raw) -> X16 = half(lrelu(Y)*scale+shift)
__global__ void transform_kernel(const float* __restrict__ Y, int n4,
                                 const float* __restrict__ scale,
                                 const float* __restrict__ shift,
                                 uint32_t* __restrict__ out) {
    int i = blockIdx.x * 256 + threadIdx.x;
    if (i >= n4) return;
    int cg = i & 31;
    float4 v  = __ldg((const float4*)Y + i);
    float4 sc = __ldg((const float4*)scale + cg);
    float4 sh = __ldg((const float4*)shift + cg);
    float a = fmaf(lrelu(v.x), sc.x, sh.x);
    float b = fmaf(lrelu(v.y), sc.y, sh.y);
    float c = fmaf(lrelu(v.z), sc.z, sh.z);
    float d = fmaf(lrelu(v.w), sc.w, sh.w);
    ((uint2*)out)[i] = make_uint2(pk2(a, b), pk2(c, d));
}

// ---------------------------------------------------------------------------
// Fused block-aggregated compaction (round-10 proven)
// ---------------------------------------------------------------------------
__global__ void compact_fused(const int* __restrict__ map31, const int* __restrict__ map13,
                              const int* __restrict__ mpool, int N, int M,
                              int2* __restrict__ p31, int2* __restrict__ p13,
                              int2* __restrict__ pP, int* __restrict__ cnt) {
    const int tid  = threadIdx.x;
    const int lane = tid & 31, wid = tid >> 5;
    long long gi = (long long)blockIdx.x * 512 + tid;
    const long long n1 = 9LL * N, n2 = 18LL * N, n3 = n2 + 27LL * M;

    int key = 63, outIdx = 0, idx = -1;
    if (gi < n1) {
        int i = (int)gi;
        int k = i / N;
        outIdx = i - k * N;
        if (k != 4) idx = __ldg(&map31[i]);
        key = k;
    } else if (gi < n2) {
        int i = (int)(gi - n1);
        int k = i / N;
        outIdx = i - k * N;
        if (k != 4) idx = __ldg(&map13[i]);
        key = 16 + k;
    } else if (gi < n3) {
        int i = (int)(gi - n2);
        int k = i / M;
        outIdx = i - k * M;
        idx = __ldg(&mpool[i]);
        key = 32 + k;
    }
    const bool valid = (idx >= 0);

    unsigned samek  = __match_any_sync(0xffffffffu, key);
    unsigned voters = samek & __ballot_sync(0xffffffffu, valid);
    int leader = __ffs(voters) - 1;
    bool isLeader = valid && (lane == leader);
    unsigned gl = __ballot_sync(0xffffffffu, isLeader);

    __shared__ int eKey[32], eCnt[32], eBase[32];
    if (tid < 32) eKey[tid] = -1;
    __syncthreads();

    int slot = -1;
    if (valid) {
        slot = wid * 2 + __popc(gl & ((1u << leader) - 1u));
        if (isLeader) { eKey[slot] = key; eCnt[slot] = __popc(voters); }
    }
    __syncthreads();

    if (tid == 0) {
#pragma unroll 1
        for (int e = 0; e < 32; ++e) {
            int k = eKey[e];
            if (k < 0) continue;
            bool first = true;
            for (int f = 0; f < e; ++f)
                if (eKey[f] == k) { first = false; break; }
            if (!first) continue;
            int tot = 0;
            for (int f = e; f < 32; ++f)
                if (eKey[f] == k) tot += eCnt[f];
            int b = atomicAdd(&cnt[k], tot);
            for (int f = e; f < 32; ++f)
                if (eKey[f] == k) { eBase[f] = b; b += eCnt[f]; }
        }
    }
    __syncthreads();

    if (valid) {
        int rank = __popc(voters & ((1u << lane) - 1u));
        int base = eBase[slot] + rank;
        if (key < 16)       p31[(size_t)key * N + base]        = make_int2(outIdx, idx);
        else if (key < 32)  p13[(size_t)(key - 16) * N + base] = make_int2(outIdx, idx);
        else                pP[(size_t)(key - 32) * M + base]  = make_int2(outIdx, idx);
    }
}

__global__ void pad_all(const int* __restrict__ cnt, int N, int M,
                        int2* __restrict__ p31, int2* __restrict__ p13,
                        int2* __restrict__ pP) {
    int b = blockIdx.x;
    int2* pairs; int c;
    if (b < 9)       { c = cnt[b];           pairs = p31 + (size_t)b * N; }
    else if (b < 18) { c = cnt[16 + b - 9];  pairs = p13 + (size_t)(b - 9) * N; }
    else             { c = cnt[32 + b - 18]; pairs = pP  + (size_t)(b - 18) * M; }
    int e = ((c + TM - 1) / TM) * TM;
    for (int j = c + threadIdx.x; j < e; j += blockDim.x)
        pairs[j] = make_int2(-1, 0);
}

__global__ void build_dir_all(const int* __restrict__ cnt, int N, int M,
                              int* __restrict__ dTap, int* __restrict__ dBase,
                              int* __restrict__ ntOut) {
    int which = blockIdx.x;
    const int* c = cnt + (which == 0 ? 0 : which == 1 ? 16 : 32);
    int K   = which == 2 ? 27 : 9;
    int cap = which == 2 ? M : N;
    int* tileTap  = dTap  + which * 20000;
    int* tileBase = dBase + which * 20000;
    __shared__ int ntk[32], off[32];
    if (threadIdx.x == 0) {
        int t = 0;
        for (int k = 0; k < K; ++k) {
            off[k] = t;
            ntk[k] = (c[k] + TM - 1) / TM;
            t += ntk[k];
        }
        ntOut[which] = t;
    }
    __syncthreads();
    for (int k = 0; k < K; ++k)
        for (int j = threadIdx.x; j < ntk[k]; j += blockDim.x) {
            tileTap[off[k] + j]  = k;
            tileBase[off[k] + j] = k * cap + j * TM;
        }
}

// ---------------------------------------------------------------------------
// fp16 MMA core over one 64-float chunk (32 half2 = 4 K-blocks of 16).
// ---------------------------------------------------------------------------
__device__ __forceinline__ void core16(float (*acc)[4][4],
                                       const uint32_t* __restrict__ As,
                                       const uint32_t* __restrict__ Bs,
                                       int mb, int nb, int lane) {
    const int l3 = lane & 3, l2 = lane >> 2;
#pragma unroll
    for (int kb = 0; kb < 4; ++kb) {
        const int ks2 = kb * 8;
        uint32_t bf[4][2];
#pragma unroll
        for (int na = 0; na < 4; ++na) {
            bf[na][0] = Bs[(ks2 + l3) * BSTR2 + nb + na * 8 + l2];
            bf[na][1] = Bs[(ks2 + 4 + l3) * BSTR2 + nb + na * 8 + l2];
        }
#pragma unroll
        for (int ma = 0; ma < 4; ++ma) {
            const int mrow = mb + ma * 16 + l2;
            uint32_t af[4];
            af[0] = As[mrow * ASTR2 + ks2 + l3];
            af[1] = As[(mrow + 8) * ASTR2 + ks2 + l3];
            af[2] = As[mrow * ASTR2 + ks2 + 4 + l3];
            af[3] = As[(mrow + 8) * ASTR2 + ks2 + 4 + l3];
#pragma unroll
            for (int na = 0; na < 4; ++na) mma16n8k16(acc[ma][na], af, bf[na]);
        }
    }
}

// ---------------------------------------------------------------------------
// Dense center-tap GEMM over fp16 features: Out[m] = X[m] @ Wc
// ---------------------------------------------------------------------------
template<int CIN>
__global__ void __launch_bounds__(256, 2) center_kernel(
    const uint32_t* __restrict__ X, const uint32_t* __restrict__ Wt, int M,
    float* __restrict__ Out)
{
    __shared__ uint32_t As[TM * ASTR2];
    __shared__ uint32_t Bs[32 * BSTR2];

    const int tid  = threadIdx.x;
    const int m0   = blockIdx.x * TM;
    const int wid  = tid >> 5, lane = tid & 31;
    const int mb   = (wid & 1) * 64, nb = (wid >> 1) * 32;
    const int row  = tid >> 1, half = tid & 1;
    constexpr int ROWU   = CIN / 2;     // uint32 per feature row
    constexpr int CHUNKS = CIN / 64;

    float acc[4][4][4];
#pragma unroll
    for (int ma = 0; ma < 4; ++ma)
#pragma unroll
        for (int na = 0; na < 4; ++na)
#pragma unroll
            for (int p = 0; p < 4; ++p) acc[ma][na][p] = 0.f;

    const int m = m0 + row;
    const bool vrow = m < M;
    const uint32_t* src = X + (size_t)(vrow ? m : 0) * ROWU;

    uint4 qa[4];
    // prefetch chunk 0 A (16 uint = 32 halves per thread)
#pragma unroll
    for (int j = 0; j < 4; ++j)
        qa[j] = vrow ? __ldg((const uint4*)(src + half * 16) + j)
                     : make_uint4(0, 0, 0, 0);

#pragma unroll
    for (int c = 0; c < CHUNKS; ++c) {
        __syncthreads();
        {
            uint32_t* ap = &As[row * ASTR2 + half * 16];
#pragma unroll
            for (int j = 0; j < 4; ++j) *(uint4*)(ap + j * 4) = qa[j];
        }
        {
            const int c02 = c * 32;
#pragma unroll
            for (int j = 0; j < 4; ++j) {
                int i2 = tid + j * 256;
                int kk2 = i2 >> 5, c4 = (i2 & 31) << 2;
                uint4 b = __ldg((const uint4*)(Wt + (size_t)(c02 + kk2) * CO + c4));
                *(uint4*)&Bs[kk2 * BSTR2 + c4] = b;
            }
        }
        __syncthreads();
        if (c + 1 < CHUNKS) {
#pragma unroll
            for (int j = 0; j < 4; ++j)
                qa[j] = vrow ? __ldg((const uint4*)(src + (c + 1) * 32 + half * 16) + j)
                             : make_uint4(0, 0, 0, 0);
        }
        core16(acc, As, Bs, mb, nb, lane);
    }

    const int l3 = lane & 3, l2 = lane >> 2;
#pragma unroll
    for (int ma = 0; ma < 4; ++ma) {
        int r0 = m0 + mb + ma * 16 + l2;
        int r1 = r0 + 8;
#pragma unroll
        for (int na = 0; na < 4; ++na) {
            int col = nb + na * 8 + 2 * l3;
            if (r0 < M)
                *(float2*)&Out[(size_t)r0 * CO + col] = make_float2(acc[ma][na][0], acc[ma][na][1]);
            if (r1 < M)
                *(float2*)&Out[(size_t)r1 * CO + col] = make_float2(acc[ma][na][2], acc[ma][na][3]);
        }
    }
}

// ---------------------------------------------------------------------------
// Scatter-GEMM over compacted tap tiles (fp16 features); red.global.add epilogue
// ---------------------------------------------------------------------------
template<int CIN>
__global__ void __launch_bounds__(256, 2) scatter_kernel(
    const uint32_t* __restrict__ X, const uint32_t* __restrict__ Wt,
    const int* __restrict__ tileTap, const int* __restrict__ tileBase,
    const int* __restrict__ ntPtr, const int2* __restrict__ pairs,
    float* __restrict__ Out)
{
    __shared__ uint32_t As[TM * ASTR2];
    __shared__ uint32_t Bs[32 * BSTR2];
    __shared__ int   sM[TM], sI[TM];

    const int tid  = threadIdx.x;
    const int wid  = tid >> 5, lane = tid & 31;
    const int mb   = (wid & 1) * 64, nb = (wid >> 1) * 32;
    const int row  = tid >> 1, half = tid & 1;
    const int l3   = lane & 3, l2 = lane >> 2;
    constexpr int ROWU   = CIN / 2;
    constexpr int CHUNKS = CIN / 64;

    const int nTiles = __ldg(ntPtr);

    for (int t = blockIdx.x; t < nTiles; t += gridDim.x) {
        __syncthreads();
        const int k    = __ldg(&tileTap[t]);
        const int base = __ldg(&tileBase[t]);
        if (tid < TM) {
            int2 pr = __ldg(&pairs[(size_t)base + tid]);
            sM[tid] = pr.x;
            sI[tid] = pr.y;
        }
        __syncthreads();
        const uint32_t* Wk = Wt + (size_t)k * ROWU * CO;
        const uint32_t* src = X + (size_t)sI[row] * ROWU;

        float acc[4][4][4];
#pragma unroll
        for (int ma = 0; ma < 4; ++ma)
#pragma unroll
            for (int na = 0; na < 4; ++na)
#pragma unroll
                for (int p = 0; p < 4; ++p) acc[ma][na][p] = 0.f;

        uint4 qa[4];
#pragma unroll
        for (int j = 0; j < 4; ++j)
            qa[j] = __ldg((const uint4*)(src + half * 16) + j);

#pragma unroll
        for (int c = 0; c < CHUNKS; ++c) {
            __syncthreads();
            {
                uint32_t* ap = &As[row * ASTR2 + half * 16];
#pragma unroll
                for (int j = 0; j < 4; ++j) *(uint4*)(ap + j * 4) = qa[j];
            }
            {
                const int c02 = c * 32;
#pragma unroll
                for (int j = 0; j < 4; ++j) {
                    int i2 = tid + j * 256;
                    int kk2 = i2 >> 5, c4 = (i2 & 31) << 2;
                    uint4 b = __ldg((const uint4*)(Wk + (size_t)(c02 + kk2) * CO + c4));
                    *(uint4*)&Bs[kk2 * BSTR2 + c4] = b;
                }
            }
            __syncthreads();
            if (c + 1 < CHUNKS) {
#pragma unroll
                for (int j = 0; j < 4; ++j)
                    qa[j] = __ldg((const uint4*)(src + (c + 1) * 32 + half * 16) + j);
            }
            core16(acc, As, Bs, mb, nb, lane);
        }

#pragma unroll
        for (int ma = 0; ma < 4; ++ma) {
            int lr0 = mb + ma * 16 + l2;
            int m0r = sM[lr0];
            int m1r = sM[lr0 + 8];
#pragma unroll
            for (int na = 0; na < 4; ++na) {
                int col = nb + na * 8 + 2 * l3;
                if (m0r >= 0) redadd2(Out + (size_t)m0r * CO + col, acc[ma][na][0], acc[ma][na][1]);
                if (m1r >= 0) redadd2(Out + (size_t)m1r * CO + col, acc[ma][na][2], acc[ma][na][3]);
            }
        }
    }
}

// ---------------------------------------------------------------------------
// BN stats on raw conv output (applies lrelu)
// ---------------------------------------------------------------------------
__global__ void stats_kernel(const float* __restrict__ Y, int N, float* __restrict__ part) {
    int c    = threadIdx.x & 127;
    int half = threadIdx.x >> 7;
    int rows = (N + gridDim.x - 1) / gridDim.x;
    int r0   = blockIdx.x * rows;
    int r1   = min(N, r0 + rows);
    float s = 0.f, q = 0.f;
    for (int r = r0 + half; r < r1; r += 2) {
        float x = lrelu(__ldg(&Y[(size_t)r * 128 + c]));
        s += x; q += x * x;
    }
    __shared__ float sh[256];
    sh[threadIdx.x] = s; __syncthreads();
    if (half == 0) part[(size_t)blockIdx.x * 256 + c] = sh[c] + sh[128 + c];
    __syncthreads();
    sh[threadIdx.x] = q; __syncthreads();
    if (half == 0) part[(size_t)blockIdx.x * 256 + 128 + c] = sh[c] + sh[128 + c];
}

__global__ void reduce1_kernel(const float* __restrict__ part, int nb,
                               float* __restrict__ part2) {
    int rpb = (nb + 63) >> 6;
    int r0  = blockIdx.x * rpb;
    int r1  = min(nb, r0 + rpb);
    float s = 0.f;
    for (int r = r0; r < r1; ++r) s += part[(size_t)r * 256 + threadIdx.x];
    part2[blockIdx.x * 256 + threadIdx.x] = s;
}

__global__ void reduce2_kernel(const float* __restrict__ part2, float invn,
                               const float* __restrict__ g, const float* __restrict__ b,
                               float* __restrict__ scale, float* __restrict__ shift) {
    int c = threadIdx.x;
    float s = 0.f, q = 0.f;
#pragma unroll
    for (int j = 0; j < 64; ++j) {
        s += part2[j * 256 + c];
        q += part2[j * 256 + 128 + c];
    }
    float mean = s * invn;
    float var  = q * invn - mean * mean;
    float sc   = g[c] * rsqrtf(var + 1e-5f);
    scale[c] = sc;
    shift[c] = b[c] - mean * sc;
}

// resA = BN3(lrelu(y4)) + BN1(lrelu(y2)); also writes fp16 copy for the pool
__global__ void add_bn_kernel(const float* __restrict__ y4, const float* __restrict__ y2,
                              const float* __restrict__ sc4, const float* __restrict__ sh4,
                              const float* __restrict__ sc2, const float* __restrict__ sh2,
                              float* __restrict__ out, uint32_t* __restrict__ out16, int n4) {
    int i = blockIdx.x * blockDim.x + threadIdx.x;
    if (i >= n4) return;
    int cg = i & 31;
    float4 a  = __ldg((const float4*)y4 + i);
    float4 c  = __ldg((const float4*)y2 + i);
    float4 s4 = __ldg((const float4*)sc4 + cg);
    float4 h4 = __ldg((const float4*)sh4 + cg);
    float4 s2 = __ldg((const float4*)sc2 + cg);
    float4 h2 = __ldg((const float4*)sh2 + cg);
    float4 o;
    o.x = fmaf(lrelu(a.x), s4.x, h4.x) + fmaf(lrelu(c.x), s2.x, h2.x);
    o.y = fmaf(lrelu(a.y), s4.y, h4.y) + fmaf(lrelu(c.y), s2.y, h2.y);
    o.z = fmaf(lrelu(a.z), s4.z, h4.z) + fmaf(lrelu(c.z), s2.z, h2.z);
    o.w = fmaf(lrelu(a.w), s4.w, h4.w) + fmaf(lrelu(c.w), s2.w, h2.w);
    ((float4*)out)[i] = o;
    ((uint2*)out16)[i] = make_uint2(pk2(o.x, o.y), pk2(o.z, o.w));
}

extern "C" void kernel_launch(void* const* d_in, const int* in_sizes, int n_in,
                              void* d_out, int out_size) {
    const float* feats = (const float*)d_in[0];
    const int*   map31 = (const int*)d_in[1];
    const int*   map13 = (const int*)d_in[2];
    const int*   mpool = (const int*)d_in[3];
    const float* W1    = (const float*)d_in[4];
    const float* W1_2  = (const float*)d_in[5];
    const float* W2    = (const float*)d_in[6];
    const float* W3    = (const float*)d_in[7];
    const float* Wp    = (const float*)d_in[8];
    const float* g0    = (const float*)d_in[9];
    const float* b0    = (const float*)d_in[10];
    const float* g0_2  = (const float*)d_in[11];
    const float* b0_2  = (const float*)d_in[12];
    const float* g1    = (const float*)d_in[13];
    const float* b1    = (const float*)d_in[14];
    const float* g2    = (const float*)d_in[15];
    const float* b2    = (const float*)d_in[16];

    int N = in_sizes[0] / 64;
    int M = in_sizes[3] / 27;

    float *Y1, *Y2, *Y4, *part, *part2, *scaleA, *shiftA;
    uint32_t *F16, *X16, *Wt;
    int2 *p31, *p13, *pP;
    int  *cnt, *dTap, *dBase, *nt;
    cudaGetSymbolAddress((void**)&Y1, g_Y1);
    cudaGetSymbolAddress((void**)&Y2, g_Y2);
    cudaGetSymbolAddress((void**)&Y4, g_Y4);
    cudaGetSymbolAddress((void**)&F16, g_F16);
    cudaGetSymbolAddress((void**)&X16, g_X16);
    cudaGetSymbolAddress((void**)&part, g_part);
    cudaGetSymbolAddress((void**)&part2, g_part2);
    cudaGetSymbolAddress((void**)&scaleA, g_scale);
    cudaGetSymbolAddress((void**)&shiftA, g_shift);
    cudaGetSymbolAddress((void**)&p31, g_pairs31);
    cudaGetSymbolAddress((void**)&p13, g_pairs13);
    cudaGetSymbolAddress((void**)&pP,  g_pairsP);
    cudaGetSymbolAddress((void**)&cnt, g_cnt);
    cudaGetSymbolAddress((void**)&dTap, g_dirTap);
    cudaGetSymbolAddress((void**)&dBase, g_dirBase);
    cudaGetSymbolAddress((void**)&nt, g_nt);
    cudaGetSymbolAddress((void**)&Wt, g_Wt);

    float* resB = (float*)d_out;
    float* resA = (float*)d_out + (size_t)M * CO;

    int nb = (N + TM - 1) / TM;
    int n4_64  = N * 16;    // float4s in a 64ch tensor
    int n4_128 = N * 32;    // float4s in a 128ch tensor
    float invn = 1.0f / (float)N;

    int* dTap31 = dTap;          int* dBase31 = dBase;
    int* dTap13 = dTap + 20000;  int* dBase13 = dBase + 20000;
    int* dTapP  = dTap + 40000;  int* dBaseP  = dBase + 40000;

    uint32_t* T1  = Wt;
    uint32_t* T12 = Wt + 36864;
    uint32_t* T2  = Wt + 110592;
    uint32_t* T3  = Wt + 147456;
    uint32_t* Tp  = Wt + 221184;
    cvtw_all<<<(442368 + 255) / 256, 256>>>(W1, W1_2, W2, W3, Wp, Wt);
    cvt_feats<<<(n4_64 + 255) / 256, 256>>>(feats, n4_64, F16);

    // ---- one-time compaction ----
    cudaMemsetAsync(cnt, 0, 64 * sizeof(int));
    long long total = 18LL * N + 27LL * M;
    int cgrid = (int)((total + 511) / 512);
    compact_fused<<<cgrid, 512>>>(map31, map13, mpool, N, M, p31, p13, pP, cnt);
    pad_all<<<45, 128>>>(cnt, N, M, p31, p13, pP);
    build_dir_all<<<3, 256>>>(cnt, N, M, dTap, dBase, nt);

    // ---- conv1 (3,1,3): F16 -> Y1 raw ----
    center_kernel<64><<<nb, 256>>>(F16, T1 + (size_t)4 * 32 * CO, N, Y1);
    scatter_kernel<64><<<SCATTER_GRID, 256>>>(F16, T1, dTap31, dBase31, nt + 0, p31, Y1);
    stats_kernel<<<STATS_GB, 256>>>(Y1, N, part);
    reduce1_kernel<<<64, 256>>>(part, STATS_GB, part2);
    reduce2_kernel<<<1, 128>>>(part2, invn, g0, b0, scaleA + 0, shiftA + 0);

    // ---- conv1_2 (1,3,3): BN0(lrelu(Y1)) -> X16 -> Y2 raw ----
    transform_kernel<<<(n4_128 + 255) / 256, 256>>>(Y1, n4_128, scaleA + 0, shiftA + 0, X16);
    center_kernel<128><<<nb, 256>>>(X16, T12 + (size_t)4 * 64 * CO, N, Y2);
    scatter_kernel<128><<<SCATTER_GRID, 256>>>(X16, T12, dTap13, dBase13, nt + 1, p13, Y2);
    stats_kernel<<<STATS_GB, 256>>>(Y2, N, part);
    reduce1_kernel<<<64, 256>>>(part, STATS_GB, part2);
    reduce2_kernel<<<1, 128>>>(part2, invn, g0_2, b0_2, scaleA + 128, shiftA + 128);

    // ---- conv2 (1,3,3): F16 -> Y3 (reuse Y1 buffer) ----
    center_kernel<64><<<nb, 256>>>(F16, T2 + (size_t)4 * 32 * CO, N, Y1);
    scatter_kernel<64><<<SCATTER_GRID, 256>>>(F16, T2, dTap13, dBase13, nt + 1, p13, Y1);
    stats_kernel<<<STATS_GB, 256>>>(Y1, N, part);
    reduce1_kernel<<<64, 256>>>(part, STATS_GB, part2);
    reduce2_kernel<<<1, 128>>>(part2, invn, g1, b1, scaleA + 256, shiftA + 256);

    // ---- conv3 (3,1,3): BN2(lrelu(Y3)) -> X16 -> Y4 raw ----
    transform_kernel<<<(n4_128 + 255) / 256, 256>>>(Y1, n4_128, scaleA + 256, shiftA + 256, X16);
    center_kernel<128><<<nb, 256>>>(X16, T3 + (size_t)4 * 64 * CO, N, Y4);
    scatter_kernel<128><<<SCATTER_GRID, 256>>>(X16, T3, dTap31, dBase31, nt + 0, p31, Y4);
    stats_kernel<<<STATS_GB, 256>>>(Y4, N, part);
    reduce1_kernel<<<64, 256>>>(part, STATS_GB, part2);
    reduce2_kernel<<<1, 128>>>(part2, invn, g2, b2, scaleA + 384, shiftA + 384);

    // ---- resA = BN3(lrelu(Y4)) + BN1(lrelu(Y2)); X16 = half(resA) ----
    add_bn_kernel<<<(n4_128 + 255) / 256, 256>>>(Y4, Y2, scaleA + 384, shiftA + 384,
                                                 scaleA + 128, shiftA + 128, resA, X16, n4_128);

    // ---- pool conv (3,3,3)/(2,2,1): X16(resA) -> resB ----
    cudaMemsetAsync(resB, 0, (size_t)M * CO * sizeof(float));
    scatter_kernel<128><<<SCATTER_GRID, 256>>>(X16, Tp, dTapP, dBaseP, nt + 2, pP, resB);
}